// round 1
// baseline (speedup 1.0000x reference)
#include <cuda_runtime.h>
#include <cuda_bf16.h>
#include <cstdint>
#include <math.h>

// ---------------------------------------------------------------------------
// GPT2 attention block, fp32 baseline:
//   qkv = x @ W_attn + b_attn            (4096x1024 @ 1024x3072)
//   causal flash attention, 16 heads, hd=64
//   out = att @ W_proj + b_proj          (4096x1024 @ 1024x1024)
// ---------------------------------------------------------------------------

#define S_LEN 4096
#define C_DIM 1024
#define H_NUM 16
#define HD    64

// Scratch (allocation-free rule: __device__ globals)
__device__ float g_qkv[(size_t)S_LEN * 3 * C_DIM];   // 48 MB
__device__ float g_att[(size_t)S_LEN * C_DIM];       // 16 MB

// ---------------------------------------------------------------------------
// SGEMM with bias: C[M,N] = A[M,K] @ B[K,N] + bias[N]
// 128x128 block tile, BK=8, 256 threads, 8x8 per-thread micro-tile.
// Conflict-free smem reads via split 4+4 groups (rows ty*4 / 64+ty*4, etc.)
// ---------------------------------------------------------------------------
__global__ __launch_bounds__(256) void sgemm_bias_kernel(
    int M, int N, int K,
    const float* __restrict__ A, const float* __restrict__ B,
    const float* __restrict__ bias, float* __restrict__ C)
{
    constexpr int BM = 128, BN = 128, BK = 8;
    __shared__ float As[BK][BM];
    __shared__ float Bs[BK][BN];

    const int tid = threadIdx.x;
    const int tx  = tid & 15;   // 0..15
    const int ty  = tid >> 4;   // 0..15
    const int bm  = blockIdx.y * BM;
    const int bn  = blockIdx.x * BN;

    // global load mapping
    const int aRow = tid >> 1;            // 0..127
    const int aCol = (tid & 1) * 4;       // 0 or 4
    const int bRow = tid >> 5;            // 0..7
    const int bCol = (tid & 31) * 4;      // 0..124

    float acc[8][8];
#pragma unroll
    for (int i = 0; i < 8; i++)
#pragma unroll
        for (int j = 0; j < 8; j++) acc[i][j] = 0.f;

    const float* Aptr = A + (size_t)(bm + aRow) * K + aCol;
    const float* Bptr = B + (size_t)bRow * N + bn + bCol;

    for (int k0 = 0; k0 < K; k0 += BK) {
        float4 a4 = *(const float4*)(Aptr + k0);
        As[aCol + 0][aRow] = a4.x;
        As[aCol + 1][aRow] = a4.y;
        As[aCol + 2][aRow] = a4.z;
        As[aCol + 3][aRow] = a4.w;
        float4 b4 = *(const float4*)(Bptr + (size_t)k0 * N);
        *(float4*)(&Bs[bRow][bCol]) = b4;
        __syncthreads();

#pragma unroll
        for (int kk = 0; kk < BK; kk++) {
            float ar[8], br[8];
            *(float4*)(ar)     = *(const float4*)(&As[kk][ty * 4]);
            *(float4*)(ar + 4) = *(const float4*)(&As[kk][64 + ty * 4]);
            *(float4*)(br)     = *(const float4*)(&Bs[kk][tx * 4]);
            *(float4*)(br + 4) = *(const float4*)(&Bs[kk][64 + tx * 4]);
#pragma unroll
            for (int i = 0; i < 8; i++)
#pragma unroll
                for (int j = 0; j < 8; j++)
                    acc[i][j] = fmaf(ar[i], br[j], acc[i][j]);
        }
        __syncthreads();
    }

    // epilogue: bias + store
#pragma unroll
    for (int ih = 0; ih < 2; ih++) {
#pragma unroll
        for (int ii = 0; ii < 4; ii++) {
            int r = bm + ih * 64 + ty * 4 + ii;
#pragma unroll
            for (int jh = 0; jh < 2; jh++) {
                int c = bn + jh * 64 + tx * 4;
                float4 o;
                o.x = acc[ih * 4 + ii][jh * 4 + 0] + bias[c + 0];
                o.y = acc[ih * 4 + ii][jh * 4 + 1] + bias[c + 1];
                o.z = acc[ih * 4 + ii][jh * 4 + 2] + bias[c + 2];
                o.w = acc[ih * 4 + ii][jh * 4 + 3] + bias[c + 3];
                *(float4*)(C + (size_t)r * N + c) = o;
            }
        }
    }
}

// ---------------------------------------------------------------------------
// Causal flash attention (fp32, online softmax).
// Grid: (S/64 q-tiles, 16 heads). 256 threads.
// Per-thread 4x4 micro-tile: rows ty+16a, cols tx+16b.
// smem: Q, K, V, P tiles 64 x 68 (padded) — dynamic smem (69632 B).
// ---------------------------------------------------------------------------
#define BQ   64
#define BKV  64
#define SSTR 68   // padded row stride (floats)

__device__ __forceinline__ float grp_max16(float v) {
#pragma unroll
    for (int m = 8; m >= 1; m >>= 1)
        v = fmaxf(v, __shfl_xor_sync(0xffffffffu, v, m));
    return v;
}
__device__ __forceinline__ float grp_sum16(float v) {
#pragma unroll
    for (int m = 8; m >= 1; m >>= 1)
        v += __shfl_xor_sync(0xffffffffu, v, m);
    return v;
}

extern __shared__ float attn_smem[];

__global__ __launch_bounds__(256) void attn_kernel(
    const float* __restrict__ qkv, float* __restrict__ out)
{
    float* Qs = attn_smem;                       // [BQ][SSTR]
    float* Ks = Qs + BQ * SSTR;                  // [BKV][SSTR]
    float* Vs = Ks + BKV * SSTR;                 // [BKV][SSTR]
    float* Ps = Vs + BKV * SSTR;                 // [BQ][SSTR]

    const int tid   = threadIdx.x;
    const int tx    = tid & 15;
    const int ty    = tid >> 4;
    const int h     = blockIdx.y;
    const int qtile = blockIdx.x;
    const int qbase = qtile * BQ;
    const float scale = 0.125f;   // 1/sqrt(64)

    // load Q tile (scaled): 64 rows x 16 float4
    for (int idx = tid; idx < BQ * (HD / 4); idx += 256) {
        int r  = idx >> 4;
        int d4 = (idx & 15) * 4;
        float4 q = *(const float4*)(qkv + (size_t)(qbase + r) * (3 * C_DIM) + h * HD + d4);
        q.x *= scale; q.y *= scale; q.z *= scale; q.w *= scale;
        *(float4*)(&Qs[r * SSTR + d4]) = q;
    }

    float mrow[4], lrow[4], o[4][4];
#pragma unroll
    for (int a = 0; a < 4; a++) {
        mrow[a] = -INFINITY;
        lrow[a] = 0.f;
#pragma unroll
        for (int b = 0; b < 4; b++) o[a][b] = 0.f;
    }

    const int njt = qtile + 1;   // causal: kv tiles 0..qtile
    for (int jt = 0; jt < njt; jt++) {
        const int kvbase = jt * BKV;
        __syncthreads();   // previous P@V done before overwriting K/V
        for (int idx = tid; idx < BKV * (HD / 4); idx += 256) {
            int r  = idx >> 4;
            int d4 = (idx & 15) * 4;
            const float* base = qkv + (size_t)(kvbase + r) * (3 * C_DIM) + h * HD + d4;
            *(float4*)(&Ks[r * SSTR + d4]) = *(const float4*)(base + C_DIM);       // K
            *(float4*)(&Vs[r * SSTR + d4]) = *(const float4*)(base + 2 * C_DIM);   // V
        }
        __syncthreads();

        // S = Q K^T  (4x4 per thread)
        float s[4][4];
#pragma unroll
        for (int a = 0; a < 4; a++)
#pragma unroll
            for (int b = 0; b < 4; b++) s[a][b] = 0.f;

        for (int d4 = 0; d4 < HD; d4 += 4) {
            float4 qa[4], kb[4];
#pragma unroll
            for (int a = 0; a < 4; a++) qa[a] = *(const float4*)(&Qs[(ty + 16 * a) * SSTR + d4]);
#pragma unroll
            for (int b = 0; b < 4; b++) kb[b] = *(const float4*)(&Ks[(tx + 16 * b) * SSTR + d4]);
#pragma unroll
            for (int a = 0; a < 4; a++)
#pragma unroll
                for (int b = 0; b < 4; b++) {
                    s[a][b] = fmaf(qa[a].x, kb[b].x, s[a][b]);
                    s[a][b] = fmaf(qa[a].y, kb[b].y, s[a][b]);
                    s[a][b] = fmaf(qa[a].z, kb[b].z, s[a][b]);
                    s[a][b] = fmaf(qa[a].w, kb[b].w, s[a][b]);
                }
        }

        // causal mask on diagonal tile
        if (jt == qtile) {
#pragma unroll
            for (int a = 0; a < 4; a++) {
                int r = ty + 16 * a;
#pragma unroll
                for (int b = 0; b < 4; b++) {
                    int c = tx + 16 * b;
                    if (c > r) s[a][b] = -INFINITY;
                }
            }
        }

        // online softmax update
#pragma unroll
        for (int a = 0; a < 4; a++) {
            float mt = fmaxf(fmaxf(s[a][0], s[a][1]), fmaxf(s[a][2], s[a][3]));
            mt = grp_max16(mt);
            float mnew  = fmaxf(mrow[a], mt);
            float alpha = __expf(mrow[a] - mnew);
            mrow[a] = mnew;
            float rs = 0.f;
#pragma unroll
            for (int b = 0; b < 4; b++) {
                float p = __expf(s[a][b] - mnew);
                s[a][b] = p;
                rs += p;
            }
            rs = grp_sum16(rs);
            lrow[a] = lrow[a] * alpha + rs;
#pragma unroll
            for (int b = 0; b < 4; b++) o[a][b] *= alpha;
        }

        // stash P
#pragma unroll
        for (int a = 0; a < 4; a++)
#pragma unroll
            for (int b = 0; b < 4; b++)
                Ps[(ty + 16 * a) * SSTR + (tx + 16 * b)] = s[a][b];
        __syncthreads();

        // O += P @ V
        for (int c = 0; c < BKV; c++) {
            float pa[4], vb[4];
#pragma unroll
            for (int a = 0; a < 4; a++) pa[a] = Ps[(ty + 16 * a) * SSTR + c];
#pragma unroll
            for (int b = 0; b < 4; b++) vb[b] = Vs[c * SSTR + tx + 16 * b];
#pragma unroll
            for (int a = 0; a < 4; a++)
#pragma unroll
                for (int b = 0; b < 4; b++)
                    o[a][b] = fmaf(pa[a], vb[b], o[a][b]);
        }
    }

    // normalize + store to [S, C] layout (head-interleaved) for proj GEMM
#pragma unroll
    for (int a = 0; a < 4; a++) {
        float inv = 1.f / lrow[a];
        int r = qbase + ty + 16 * a;
#pragma unroll
        for (int b = 0; b < 4; b++) {
            int d = tx + 16 * b;
            out[(size_t)r * C_DIM + h * HD + d] = o[a][b] * inv;
        }
    }
}

// ---------------------------------------------------------------------------
// Launch
// ---------------------------------------------------------------------------
extern "C" void kernel_launch(void* const* d_in, const int* in_sizes, int n_in,
                              void* d_out, int out_size)
{
    const float* x      = (const float*)d_in[0];
    // d_in[1] = attention_mask (exact causal triu of -1e9): handled analytically
    const float* W_attn = (const float*)d_in[2];
    const float* b_attn = (const float*)d_in[3];
    const float* W_proj = (const float*)d_in[4];
    const float* b_proj = (const float*)d_in[5];
    float* out = (float*)d_out;

    float *qkv_ptr = nullptr, *att_ptr = nullptr;
    cudaGetSymbolAddress((void**)&qkv_ptr, g_qkv);
    cudaGetSymbolAddress((void**)&att_ptr, g_att);

    // 1) qkv = x @ W_attn + b_attn
    {
        dim3 grid((3 * C_DIM) / 128, S_LEN / 128);
        sgemm_bias_kernel<<<grid, 256>>>(S_LEN, 3 * C_DIM, C_DIM,
                                         x, W_attn, b_attn, qkv_ptr);
    }

    // 2) causal flash attention
    {
        const int smem_bytes = (BQ + 2 * BKV + BQ) * SSTR * sizeof(float); // 69632
        cudaFuncSetAttribute(attn_kernel,
                             cudaFuncAttributeMaxDynamicSharedMemorySize, smem_bytes);
        dim3 grid(S_LEN / BQ, H_NUM);
        attn_kernel<<<grid, 256, smem_bytes>>>(qkv_ptr, att_ptr);
    }

    // 3) out = att @ W_proj + b_proj
    {
        dim3 grid(C_DIM / 128, S_LEN / 128);
        sgemm_bias_kernel<<<grid, 256>>>(S_LEN, C_DIM, C_DIM,
                                         att_ptr, W_proj, b_proj, out);
    }
}

// round 3
// speedup vs baseline: 1.1177x; 1.1177x over previous
#include <cuda_runtime.h>
#include <cuda_bf16.h>
#include <mma.h>
#include <cstdint>
#include <math.h>

using namespace nvcuda;

// ---------------------------------------------------------------------------
// GPT2 attention block:
//   qkv  = x @ W_attn + b_attn      -> wmma tf32 GEMM (HMMA)
//   att  = causal flash attention (fp32 scalar)
//   out  = att @ W_proj + b_proj    -> wmma tf32 GEMM (HMMA)
// ---------------------------------------------------------------------------

#define S_LEN 4096
#define C_DIM 1024
#define H_NUM 16
#define HD    64

// Scratch (__device__ globals: allocation-free rule)
__device__ float g_qkv[(size_t)S_LEN * 3 * C_DIM];   // 48 MB
__device__ float g_att[(size_t)S_LEN * C_DIM];       // 16 MB (tf32-rounded)
__device__ float g_xt [(size_t)S_LEN * C_DIM];       // 16 MB x, tf32-rounded
__device__ float g_wt [(size_t)3 * C_DIM * C_DIM];   // 12 MB W_attn^T, tf32-rounded
__device__ float g_wpt[(size_t)C_DIM * C_DIM];       //  4 MB W_proj^T, tf32-rounded

// ---------------------------------------------------------------------------
// Helpers
// ---------------------------------------------------------------------------
__device__ __forceinline__ float rna_tf32(float x) {
    uint32_t t;
    asm("cvt.rna.tf32.f32 %0, %1;" : "=r"(t) : "f"(x));
    return __uint_as_float(t);
}

__device__ __forceinline__ void cp16(void* s, const float* g) {
    uint32_t sa = (uint32_t)__cvta_generic_to_shared(s);
    asm volatile("cp.async.cg.shared.global [%0], [%1], 16;"
                 :: "r"(sa), "l"(__cvta_generic_to_global(g)));
}

// ---------------------------------------------------------------------------
// Prep kernels
// ---------------------------------------------------------------------------
__global__ __launch_bounds__(256) void cvt_tf32_kernel(
    const float4* __restrict__ in, float4* __restrict__ out, int n4)
{
    int i = blockIdx.x * 256 + threadIdx.x;
    if (i < n4) {
        float4 v = in[i];
        v.x = rna_tf32(v.x); v.y = rna_tf32(v.y);
        v.z = rna_tf32(v.z); v.w = rna_tf32(v.w);
        out[i] = v;
    }
}

// in: [K][N] row-major  ->  out: [N][K] row-major, tf32-rounded
__global__ __launch_bounds__(256) void transpose_cvt_kernel(
    const float* __restrict__ in, float* __restrict__ out, int K, int N)
{
    __shared__ float t[32][33];
    const int tx = threadIdx.x & 31;
    const int ty = threadIdx.x >> 5;
    const int n0 = blockIdx.x * 32;
    const int k0 = blockIdx.y * 32;
#pragma unroll
    for (int i = 0; i < 32; i += 8)
        t[ty + i][tx] = rna_tf32(in[(size_t)(k0 + ty + i) * N + n0 + tx]);
    __syncthreads();
#pragma unroll
    for (int i = 0; i < 32; i += 8)
        out[(size_t)(n0 + ty + i) * K + k0 + tx] = t[tx][ty + i];
}

// ---------------------------------------------------------------------------
// wmma tf32 GEMM:  C[M,N] = A[M,K] @ Bt[N,K]^T + bias[N]
// CTA 128x128, BK=32, 3-stage cp.async pipeline, 8 warps (2x4),
// warp tile 64x32 = 4x2 wmma(16x16x8) accumulators.
// ---------------------------------------------------------------------------
#define GBM 128
#define GBN 128
#define GBK 32
#define ALD 36
#define STAGE_F (GBM * ALD + GBN * ALD)
#define EPI_LD 132
#define EPI_OFF (3 * STAGE_F)
#define GSMEM_DYN ((EPI_OFF + GBM * EPI_LD) * 4)

extern __shared__ float gsm[];

__global__ __launch_bounds__(256, 1) void gemm_tf32_kernel(
    int M, int N, int K,
    const float* __restrict__ A,
    const float* __restrict__ Bt,
    const float* __restrict__ bias,
    float* __restrict__ C)
{
    const int tid = threadIdx.x;
    const int wid = tid >> 5;
    const int wm  = (wid >> 2) * 64;
    const int wn  = (wid & 3) * 32;
    const int bm  = blockIdx.y * GBM;
    const int bn  = blockIdx.x * GBN;
    const int nchunks = K / GBK;

    wmma::fragment<wmma::accumulator, 16, 16, 8, float> cfr[4][2];
#pragma unroll
    for (int i = 0; i < 4; i++)
#pragma unroll
        for (int j = 0; j < 2; j++) wmma::fill_fragment(cfr[i][j], 0.f);

    auto load_stage = [&](int s, int c) {
        float* As = gsm + s * STAGE_F;
        float* Bs = As + GBM * ALD;
        const int k0 = c * GBK;
        const float* Ab = A  + (size_t)bm * K + k0;
        const float* Bb = Bt + (size_t)bn * K + k0;
#pragma unroll
        for (int i = 0; i < 4; i++) {
            int q = tid + i * 256;
            int r = q >> 3, cc = (q & 7) << 2;
            cp16(As + r * ALD + cc, Ab + (size_t)r * K + cc);
        }
#pragma unroll
        for (int i = 0; i < 4; i++) {
            int q = tid + i * 256;
            int r = q >> 3, cc = (q & 7) << 2;
            cp16(Bs + r * ALD + cc, Bb + (size_t)r * K + cc);
        }
        asm volatile("cp.async.commit_group;" ::: "memory");
    };

    load_stage(0, 0);
    load_stage(1, 1);

    for (int c = 0; c < nchunks; c++) {
        if (c + 2 < nchunks)
            asm volatile("cp.async.wait_group 1;" ::: "memory");
        else
            asm volatile("cp.async.wait_group 0;" ::: "memory");
        __syncthreads();

        if (c + 2 < nchunks) load_stage((c + 2) % 3, c + 2);

        const float* As = gsm + (c % 3) * STAGE_F;
        const float* Bs = As + GBM * ALD;

#pragma unroll
        for (int ks = 0; ks < GBK / 8; ks++) {
            const int k0 = ks * 8;
            wmma::fragment<wmma::matrix_a, 16, 16, 8,
                           wmma::precision::tf32, wmma::row_major> afr[4];
            wmma::fragment<wmma::matrix_b, 16, 16, 8,
                           wmma::precision::tf32, wmma::col_major> bfr[2];
#pragma unroll
            for (int i = 0; i < 4; i++)
                wmma::load_matrix_sync(afr[i], As + (wm + i * 16) * ALD + k0, ALD);
#pragma unroll
            for (int j = 0; j < 2; j++)
                wmma::load_matrix_sync(bfr[j], Bs + (wn + j * 16) * ALD + k0, ALD);
#pragma unroll
            for (int i = 0; i < 4; i++)
#pragma unroll
                for (int j = 0; j < 2; j++)
                    wmma::mma_sync(cfr[i][j], afr[i], bfr[j], cfr[i][j]);
        }
        __syncthreads();
    }

    float* Ep = gsm + EPI_OFF;
#pragma unroll
    for (int i = 0; i < 4; i++)
#pragma unroll
        for (int j = 0; j < 2; j++)
            wmma::store_matrix_sync(Ep + (wm + i * 16) * EPI_LD + wn + j * 16,
                                    cfr[i][j], EPI_LD, wmma::mem_row_major);
    __syncthreads();

    for (int idx = tid; idx < GBM * (GBN / 4); idx += 256) {
        int r  = idx >> 5;
        int c4 = (idx & 31) * 4;
        const float* e = Ep + r * EPI_LD + c4;
        const float* b = bias + bn + c4;
        float4 o;
        o.x = e[0] + b[0];
        o.y = e[1] + b[1];
        o.z = e[2] + b[2];
        o.w = e[3] + b[3];
        *(float4*)(C + (size_t)(bm + r) * N + bn + c4) = o;
    }
}

// ---------------------------------------------------------------------------
// Causal flash attention (fp32, online softmax). Output tf32-rounded.
// ---------------------------------------------------------------------------
#define BQ   64
#define BKV  64
#define SSTR 68

__device__ __forceinline__ float grp_max16(float v) {
#pragma unroll
    for (int m = 8; m >= 1; m >>= 1)
        v = fmaxf(v, __shfl_xor_sync(0xffffffffu, v, m));
    return v;
}
__device__ __forceinline__ float grp_sum16(float v) {
#pragma unroll
    for (int m = 8; m >= 1; m >>= 1)
        v += __shfl_xor_sync(0xffffffffu, v, m);
    return v;
}

extern __shared__ float attn_smem[];

__global__ __launch_bounds__(256) void attn_kernel(
    const float* __restrict__ qkv, float* __restrict__ out)
{
    float* Qs = attn_smem;
    float* Ks = Qs + BQ * SSTR;
    float* Vs = Ks + BKV * SSTR;
    float* Ps = Vs + BKV * SSTR;

    const int tid   = threadIdx.x;
    const int tx    = tid & 15;
    const int ty    = tid >> 4;
    const int h     = blockIdx.y;
    const int qtile = blockIdx.x;
    const int qbase = qtile * BQ;
    const float scale = 0.125f;

    for (int idx = tid; idx < BQ * (HD / 4); idx += 256) {
        int r  = idx >> 4;
        int d4 = (idx & 15) * 4;
        float4 q = *(const float4*)(qkv + (size_t)(qbase + r) * (3 * C_DIM) + h * HD + d4);
        q.x *= scale; q.y *= scale; q.z *= scale; q.w *= scale;
        *(float4*)(&Qs[r * SSTR + d4]) = q;
    }

    float mrow[4], lrow[4], o[4][4];
#pragma unroll
    for (int a = 0; a < 4; a++) {
        mrow[a] = -INFINITY; lrow[a] = 0.f;
#pragma unroll
        for (int b = 0; b < 4; b++) o[a][b] = 0.f;
    }

    const int njt = qtile + 1;
    for (int jt = 0; jt < njt; jt++) {
        const int kvbase = jt * BKV;
        __syncthreads();
        for (int idx = tid; idx < BKV * (HD / 4); idx += 256) {
            int r  = idx >> 4;
            int d4 = (idx & 15) * 4;
            const float* base = qkv + (size_t)(kvbase + r) * (3 * C_DIM) + h * HD + d4;
            *(float4*)(&Ks[r * SSTR + d4]) = *(const float4*)(base + C_DIM);
            *(float4*)(&Vs[r * SSTR + d4]) = *(const float4*)(base + 2 * C_DIM);
        }
        __syncthreads();

        float s[4][4];
#pragma unroll
        for (int a = 0; a < 4; a++)
#pragma unroll
            for (int b = 0; b < 4; b++) s[a][b] = 0.f;

        for (int d4 = 0; d4 < HD; d4 += 4) {
            float4 qa[4], kb[4];
#pragma unroll
            for (int a = 0; a < 4; a++) qa[a] = *(const float4*)(&Qs[(ty + 16 * a) * SSTR + d4]);
#pragma unroll
            for (int b = 0; b < 4; b++) kb[b] = *(const float4*)(&Ks[(tx + 16 * b) * SSTR + d4]);
#pragma unroll
            for (int a = 0; a < 4; a++)
#pragma unroll
                for (int b = 0; b < 4; b++) {
                    s[a][b] = fmaf(qa[a].x, kb[b].x, s[a][b]);
                    s[a][b] = fmaf(qa[a].y, kb[b].y, s[a][b]);
                    s[a][b] = fmaf(qa[a].z, kb[b].z, s[a][b]);
                    s[a][b] = fmaf(qa[a].w, kb[b].w, s[a][b]);
                }
        }

        if (jt == qtile) {
#pragma unroll
            for (int a = 0; a < 4; a++) {
                int r = ty + 16 * a;
#pragma unroll
                for (int b = 0; b < 4; b++) {
                    int c = tx + 16 * b;
                    if (c > r) s[a][b] = -INFINITY;
                }
            }
        }

#pragma unroll
        for (int a = 0; a < 4; a++) {
            float mt = fmaxf(fmaxf(s[a][0], s[a][1]), fmaxf(s[a][2], s[a][3]));
            mt = grp_max16(mt);
            float mnew  = fmaxf(mrow[a], mt);
            float alpha = __expf(mrow[a] - mnew);
            mrow[a] = mnew;
            float rs = 0.f;
#pragma unroll
            for (int b = 0; b < 4; b++) {
                float p = __expf(s[a][b] - mnew);
                s[a][b] = p;
                rs += p;
            }
            rs = grp_sum16(rs);
            lrow[a] = lrow[a] * alpha + rs;
#pragma unroll
            for (int b = 0; b < 4; b++) o[a][b] *= alpha;
        }

#pragma unroll
        for (int a = 0; a < 4; a++)
#pragma unroll
            for (int b = 0; b < 4; b++)
                Ps[(ty + 16 * a) * SSTR + (tx + 16 * b)] = s[a][b];
        __syncthreads();

        for (int c = 0; c < BKV; c++) {
            float pa[4], vb[4];
#pragma unroll
            for (int a = 0; a < 4; a++) pa[a] = Ps[(ty + 16 * a) * SSTR + c];
#pragma unroll
            for (int b = 0; b < 4; b++) vb[b] = Vs[c * SSTR + tx + 16 * b];
#pragma unroll
            for (int a = 0; a < 4; a++)
#pragma unroll
                for (int b = 0; b < 4; b++)
                    o[a][b] = fmaf(pa[a], vb[b], o[a][b]);
        }
    }

#pragma unroll
    for (int a = 0; a < 4; a++) {
        float inv = 1.f / lrow[a];
        int r = qbase + ty + 16 * a;
#pragma unroll
        for (int b = 0; b < 4; b++) {
            int d = tx + 16 * b;
            out[(size_t)r * C_DIM + h * HD + d] = rna_tf32(o[a][b] * inv);
        }
    }
}

// ---------------------------------------------------------------------------
// Launch
// ---------------------------------------------------------------------------
extern "C" void kernel_launch(void* const* d_in, const int* in_sizes, int n_in,
                              void* d_out, int out_size)
{
    const float* x      = (const float*)d_in[0];
    // d_in[1] = attention_mask: exact causal triu -> handled analytically
    const float* W_attn = (const float*)d_in[2];
    const float* b_attn = (const float*)d_in[3];
    const float* W_proj = (const float*)d_in[4];
    const float* b_proj = (const float*)d_in[5];
    float* out = (float*)d_out;

    float *qkv_p, *att_p, *xt_p, *wt_p, *wpt_p;
    cudaGetSymbolAddress((void**)&qkv_p, g_qkv);
    cudaGetSymbolAddress((void**)&att_p, g_att);
    cudaGetSymbolAddress((void**)&xt_p,  g_xt);
    cudaGetSymbolAddress((void**)&wt_p,  g_wt);
    cudaGetSymbolAddress((void**)&wpt_p, g_wpt);

    // 0) tf32 rounding / transposes
    {
        int n4 = (S_LEN * C_DIM) / 4;
        cvt_tf32_kernel<<<(n4 + 255) / 256, 256>>>(
            (const float4*)x, (float4*)xt_p, n4);

        dim3 g1(3 * C_DIM / 32, C_DIM / 32);
        transpose_cvt_kernel<<<g1, 256>>>(W_attn, wt_p, C_DIM, 3 * C_DIM);

        dim3 g2(C_DIM / 32, C_DIM / 32);
        transpose_cvt_kernel<<<g2, 256>>>(W_proj, wpt_p, C_DIM, C_DIM);
    }

    cudaFuncSetAttribute(gemm_tf32_kernel,
                         cudaFuncAttributeMaxDynamicSharedMemorySize, GSMEM_DYN);

    // 1) qkv = x @ W_attn + b_attn
    {
        dim3 grid((3 * C_DIM) / GBN, S_LEN / GBM);
        gemm_tf32_kernel<<<grid, 256, GSMEM_DYN>>>(
            S_LEN, 3 * C_DIM, C_DIM, xt_p, wt_p, b_attn, qkv_p);
    }

    // 2) causal flash attention
    {
        const int smem_bytes = (BQ + 2 * BKV + BQ) * SSTR * sizeof(float);
        cudaFuncSetAttribute(attn_kernel,
                             cudaFuncAttributeMaxDynamicSharedMemorySize, smem_bytes);
        dim3 grid(S_LEN / BQ, H_NUM);
        attn_kernel<<<grid, 256, smem_bytes>>>(qkv_p, att_p);
    }

    // 3) out = att @ W_proj + b_proj
    {
        dim3 grid(C_DIM / GBN, S_LEN / GBM);
        gemm_tf32_kernel<<<grid, 256, GSMEM_DYN>>>(
            S_LEN, C_DIM, C_DIM, att_p, wpt_p, b_proj, out);
    }
}

// round 4
// speedup vs baseline: 2.1246x; 1.9009x over previous
#include <cuda_runtime.h>
#include <cuda_bf16.h>
#include <mma.h>
#include <cstdint>
#include <math.h>

using namespace nvcuda;

#define S_LEN 4096
#define C_DIM 1024
#define H_NUM 16
#define HD    64

// Scratch (__device__ globals: allocation-free rule)
__device__ float g_qkv[(size_t)S_LEN * 3 * C_DIM];
__device__ float g_att[(size_t)S_LEN * C_DIM];
__device__ float g_xt [(size_t)S_LEN * C_DIM];
__device__ float g_wt [(size_t)3 * C_DIM * C_DIM];
__device__ float g_wpt[(size_t)C_DIM * C_DIM];

// ---------------------------------------------------------------------------
// Helpers
// ---------------------------------------------------------------------------
__device__ __forceinline__ float rna_tf32(float x) {
    uint32_t t;
    asm("cvt.rna.tf32.f32 %0, %1;" : "=r"(t) : "f"(x));
    return __uint_as_float(t);
}

__device__ __forceinline__ void cp16(void* s, const float* g) {
    uint32_t sa = (uint32_t)__cvta_generic_to_shared(s);
    asm volatile("cp.async.cg.shared.global [%0], [%1], 16;"
                 :: "r"(sa), "l"(__cvta_generic_to_global(g)));
}

// m16n8k8 tf32 mma: D = A*B + D. A row-major, B col-major.
// A frag: a0=(g, q) a1=(g+8, q) a2=(g, q+4) a3=(g+8, q+4)   [g=lane>>2, q=lane&3]
// B frag: b0=(k=q, n=g) b1=(k=q+4, n=g)
// C frag: c0=(g, 2q) c1=(g, 2q+1) c2=(g+8, 2q) c3=(g+8, 2q+1)
__device__ __forceinline__ void mma_tf32(float c[4], const uint32_t a[4],
                                         uint32_t b0, uint32_t b1) {
    asm volatile(
        "mma.sync.aligned.m16n8k8.row.col.f32.tf32.tf32.f32 "
        "{%0,%1,%2,%3}, {%4,%5,%6,%7}, {%8,%9}, {%0,%1,%2,%3};"
        : "+f"(c[0]), "+f"(c[1]), "+f"(c[2]), "+f"(c[3])
        : "r"(a[0]), "r"(a[1]), "r"(a[2]), "r"(a[3]), "r"(b0), "r"(b1));
}

// ---------------------------------------------------------------------------
// Prep kernels
// ---------------------------------------------------------------------------
__global__ __launch_bounds__(256) void cvt_tf32_kernel(
    const float4* __restrict__ in, float4* __restrict__ out, int n4)
{
    int i = blockIdx.x * 256 + threadIdx.x;
    if (i < n4) {
        float4 v = in[i];
        v.x = rna_tf32(v.x); v.y = rna_tf32(v.y);
        v.z = rna_tf32(v.z); v.w = rna_tf32(v.w);
        out[i] = v;
    }
}

__global__ __launch_bounds__(256) void transpose_cvt_kernel(
    const float* __restrict__ in, float* __restrict__ out, int K, int N)
{
    __shared__ float t[32][33];
    const int tx = threadIdx.x & 31;
    const int ty = threadIdx.x >> 5;
    const int n0 = blockIdx.x * 32;
    const int k0 = blockIdx.y * 32;
#pragma unroll
    for (int i = 0; i < 32; i += 8)
        t[ty + i][tx] = rna_tf32(in[(size_t)(k0 + ty + i) * N + n0 + tx]);
    __syncthreads();
#pragma unroll
    for (int i = 0; i < 32; i += 8)
        out[(size_t)(n0 + ty + i) * K + k0 + tx] = t[tx][ty + i];
}

// ---------------------------------------------------------------------------
// wmma tf32 GEMM:  C[M,N] = A[M,K] @ Bt[N,K]^T + bias[N]
// CTA 128x128, BK=32, 3-stage cp.async, 8 warps (2x4), warp tile 64x32.
// Epilogue buffer ALIASED onto the pipeline stages; 2 CTAs/SM target.
// ---------------------------------------------------------------------------
#define GBM 128
#define GBN 128
#define GBK 32
#define ALD 36
#define STAGE_F (GBM * ALD + GBN * ALD)
#define EPI_LD 132
#define GSMEM_DYN (3 * STAGE_F * 4)

extern __shared__ float gsm[];

__global__ __launch_bounds__(256, 2) void gemm_tf32_kernel(
    int M, int N, int K,
    const float* __restrict__ A,
    const float* __restrict__ Bt,
    const float* __restrict__ bias,
    float* __restrict__ C)
{
    const int tid = threadIdx.x;
    const int wid = tid >> 5;
    const int wm  = (wid >> 2) * 64;
    const int wn  = (wid & 3) * 32;
    const int bm  = blockIdx.y * GBM;
    const int bn  = blockIdx.x * GBN;
    const int nchunks = K / GBK;

    wmma::fragment<wmma::accumulator, 16, 16, 8, float> cfr[4][2];
#pragma unroll
    for (int i = 0; i < 4; i++)
#pragma unroll
        for (int j = 0; j < 2; j++) wmma::fill_fragment(cfr[i][j], 0.f);

    auto load_stage = [&](int s, int c) {
        float* As = gsm + s * STAGE_F;
        float* Bs = As + GBM * ALD;
        const int k0 = c * GBK;
        const float* Ab = A  + (size_t)bm * K + k0;
        const float* Bb = Bt + (size_t)bn * K + k0;
#pragma unroll
        for (int i = 0; i < 4; i++) {
            int q = tid + i * 256;
            int r = q >> 3, cc = (q & 7) << 2;
            cp16(As + r * ALD + cc, Ab + (size_t)r * K + cc);
        }
#pragma unroll
        for (int i = 0; i < 4; i++) {
            int q = tid + i * 256;
            int r = q >> 3, cc = (q & 7) << 2;
            cp16(Bs + r * ALD + cc, Bb + (size_t)r * K + cc);
        }
        asm volatile("cp.async.commit_group;" ::: "memory");
    };

    load_stage(0, 0);
    load_stage(1, 1);

    for (int c = 0; c < nchunks; c++) {
        if (c + 2 < nchunks)
            asm volatile("cp.async.wait_group 1;" ::: "memory");
        else
            asm volatile("cp.async.wait_group 0;" ::: "memory");
        __syncthreads();

        if (c + 2 < nchunks) load_stage((c + 2) % 3, c + 2);

        const float* As = gsm + (c % 3) * STAGE_F;
        const float* Bs = As + GBM * ALD;

#pragma unroll
        for (int ks = 0; ks < GBK / 8; ks++) {
            const int k0 = ks * 8;
            wmma::fragment<wmma::matrix_a, 16, 16, 8,
                           wmma::precision::tf32, wmma::row_major> afr[4];
            wmma::fragment<wmma::matrix_b, 16, 16, 8,
                           wmma::precision::tf32, wmma::col_major> bfr[2];
#pragma unroll
            for (int i = 0; i < 4; i++)
                wmma::load_matrix_sync(afr[i], As + (wm + i * 16) * ALD + k0, ALD);
#pragma unroll
            for (int j = 0; j < 2; j++)
                wmma::load_matrix_sync(bfr[j], Bs + (wn + j * 16) * ALD + k0, ALD);
#pragma unroll
            for (int i = 0; i < 4; i++)
#pragma unroll
                for (int j = 0; j < 2; j++)
                    wmma::mma_sync(cfr[i][j], afr[i], bfr[j], cfr[i][j]);
        }
        __syncthreads();
    }

    // Epilogue (aliased onto pipeline smem — all stages dead now)
    float* Ep = gsm;
#pragma unroll
    for (int i = 0; i < 4; i++)
#pragma unroll
        for (int j = 0; j < 2; j++)
            wmma::store_matrix_sync(Ep + (wm + i * 16) * EPI_LD + wn + j * 16,
                                    cfr[i][j], EPI_LD, wmma::mem_row_major);
    __syncthreads();

    for (int idx = tid; idx < GBM * (GBN / 4); idx += 256) {
        int r  = idx >> 5;
        int c4 = (idx & 31) * 4;
        const float* e = Ep + r * EPI_LD + c4;
        const float* b = bias + bn + c4;
        float4 o;
        o.x = e[0] + b[0];
        o.y = e[1] + b[1];
        o.z = e[2] + b[2];
        o.w = e[3] + b[3];
        *(float4*)(C + (size_t)(bm + r) * N + bn + c4) = o;
    }
}

// ---------------------------------------------------------------------------
// Causal flash attention with mma.sync m16n8k8 tf32.
// CTA = (head, 64-q-row tile), 128 threads = 4 warps, warp strip = 16 rows.
// Q in registers; S/O accumulators in registers; P via warp-private smem.
// ---------------------------------------------------------------------------
#define AQ   64
#define ASTR 68

extern __shared__ float attn_dyn[];

__global__ __launch_bounds__(128) void attn_mma_kernel(
    const float* __restrict__ qkv, float* __restrict__ out)
{
    float* Ks = attn_dyn;               // [64][ASTR]
    float* Vs = Ks + AQ * ASTR;         // [64][ASTR]
    float* Ps = Vs + AQ * ASTR;         // [64][ASTR]  (also Q staging)

    const int tid   = threadIdx.x;
    const int warp  = tid >> 5;
    const int lane  = tid & 31;
    const int grp   = lane >> 2;        // 0..7
    const int qd    = lane & 3;         // 0..3
    const int h     = blockIdx.y;
    const int qtile = blockIdx.x;
    const int qbase = qtile * AQ;
    const int qr0   = warp * 16 + grp;  // strip row (0..63)
    const int qr1   = qr0 + 8;

    // ---- stage Q (scaled + tf32-rounded), then lift to registers ----
#pragma unroll
    for (int i = 0; i < 8; i++) {
        int idx = tid + i * 128;
        int r = idx >> 4, d4 = (idx & 15) * 4;
        float4 q = *(const float4*)(qkv + (size_t)(qbase + r) * (3 * C_DIM) + h * HD + d4);
        q.x = rna_tf32(q.x * 0.125f); q.y = rna_tf32(q.y * 0.125f);
        q.z = rna_tf32(q.z * 0.125f); q.w = rna_tf32(q.w * 0.125f);
        *(float4*)(&Ps[r * ASTR + d4]) = q;
    }
    __syncthreads();

    uint32_t qa[8][4];
#pragma unroll
    for (int ks = 0; ks < 8; ks++) {
        int c = ks * 8 + qd;
        qa[ks][0] = __float_as_uint(Ps[qr0 * ASTR + c]);
        qa[ks][1] = __float_as_uint(Ps[qr1 * ASTR + c]);
        qa[ks][2] = __float_as_uint(Ps[qr0 * ASTR + c + 4]);
        qa[ks][3] = __float_as_uint(Ps[qr1 * ASTR + c + 4]);
    }
    __syncthreads();

    float o[8][4];
#pragma unroll
    for (int nt = 0; nt < 8; nt++)
#pragma unroll
        for (int j = 0; j < 4; j++) o[nt][j] = 0.f;
    float m0 = -INFINITY, m1 = -INFINITY, l0 = 0.f, l1 = 0.f;

    for (int jt = 0; jt <= qtile; jt++) {
        const int kvbase = jt * AQ;
        __syncthreads();
#pragma unroll
        for (int i = 0; i < 8; i++) {
            int idx = tid + i * 128;
            int r = idx >> 4, d4 = (idx & 15) * 4;
            const float* base = qkv + (size_t)(kvbase + r) * (3 * C_DIM) + h * HD + d4;
            float4 k4 = *(const float4*)(base + C_DIM);
            k4.x = rna_tf32(k4.x); k4.y = rna_tf32(k4.y);
            k4.z = rna_tf32(k4.z); k4.w = rna_tf32(k4.w);
            *(float4*)(&Ks[r * ASTR + d4]) = k4;
            float4 v4 = *(const float4*)(base + 2 * C_DIM);
            v4.x = rna_tf32(v4.x); v4.y = rna_tf32(v4.y);
            v4.z = rna_tf32(v4.z); v4.w = rna_tf32(v4.w);
            *(float4*)(&Vs[r * ASTR + d4]) = v4;
        }
        __syncthreads();

        // ---- S = Q K^T ----
        float s[8][4];
#pragma unroll
        for (int nt = 0; nt < 8; nt++)
#pragma unroll
            for (int j = 0; j < 4; j++) s[nt][j] = 0.f;

#pragma unroll
        for (int ks = 0; ks < 8; ks++) {
            const int kc = ks * 8 + qd;
#pragma unroll
            for (int nt = 0; nt < 8; nt++) {
                const float* kr = &Ks[(nt * 8 + grp) * ASTR + kc];
                mma_tf32(s[nt], qa[ks],
                         __float_as_uint(kr[0]), __float_as_uint(kr[4]));
            }
        }

        // ---- causal mask (diagonal tile only) ----
        if (jt == qtile) {
            const int rg0 = qbase + qr0, rg1 = qbase + qr1;
#pragma unroll
            for (int nt = 0; nt < 8; nt++) {
                int cg = kvbase + nt * 8 + qd * 2;
                if (cg     > rg0) s[nt][0] = -INFINITY;
                if (cg + 1 > rg0) s[nt][1] = -INFINITY;
                if (cg     > rg1) s[nt][2] = -INFINITY;
                if (cg + 1 > rg1) s[nt][3] = -INFINITY;
            }
        }

        // ---- online softmax (rows qr0, qr1; 4 threads per row) ----
        float mt0 = -INFINITY, mt1 = -INFINITY;
#pragma unroll
        for (int nt = 0; nt < 8; nt++) {
            mt0 = fmaxf(mt0, fmaxf(s[nt][0], s[nt][1]));
            mt1 = fmaxf(mt1, fmaxf(s[nt][2], s[nt][3]));
        }
        mt0 = fmaxf(mt0, __shfl_xor_sync(0xffffffffu, mt0, 1));
        mt0 = fmaxf(mt0, __shfl_xor_sync(0xffffffffu, mt0, 2));
        mt1 = fmaxf(mt1, __shfl_xor_sync(0xffffffffu, mt1, 1));
        mt1 = fmaxf(mt1, __shfl_xor_sync(0xffffffffu, mt1, 2));

        const float mn0 = fmaxf(m0, mt0), mn1 = fmaxf(m1, mt1);
        const float al0 = __expf(m0 - mn0), al1 = __expf(m1 - mn1);
        m0 = mn0; m1 = mn1;

        float rs0 = 0.f, rs1 = 0.f;
#pragma unroll
        for (int nt = 0; nt < 8; nt++) {
            s[nt][0] = __expf(s[nt][0] - mn0);
            s[nt][1] = __expf(s[nt][1] - mn0);
            s[nt][2] = __expf(s[nt][2] - mn1);
            s[nt][3] = __expf(s[nt][3] - mn1);
            rs0 += s[nt][0] + s[nt][1];
            rs1 += s[nt][2] + s[nt][3];
        }
        rs0 += __shfl_xor_sync(0xffffffffu, rs0, 1);
        rs0 += __shfl_xor_sync(0xffffffffu, rs0, 2);
        rs1 += __shfl_xor_sync(0xffffffffu, rs1, 1);
        rs1 += __shfl_xor_sync(0xffffffffu, rs1, 2);
        l0 = l0 * al0 + rs0;
        l1 = l1 * al1 + rs1;

#pragma unroll
        for (int nt = 0; nt < 8; nt++) {
            o[nt][0] *= al0; o[nt][1] *= al0;
            o[nt][2] *= al1; o[nt][3] *= al1;
        }

        // ---- P -> warp-private smem (tf32-rounded) ----
#pragma unroll
        for (int nt = 0; nt < 8; nt++) {
            float2 p0 = make_float2(rna_tf32(s[nt][0]), rna_tf32(s[nt][1]));
            *(float2*)(&Ps[qr0 * ASTR + nt * 8 + qd * 2]) = p0;
            float2 p1 = make_float2(rna_tf32(s[nt][2]), rna_tf32(s[nt][3]));
            *(float2*)(&Ps[qr1 * ASTR + nt * 8 + qd * 2]) = p1;
        }
        __syncwarp();

        // ---- O += P V ----
#pragma unroll
        for (int ks = 0; ks < 8; ks++) {
            uint32_t pa[4];
            const int pc = ks * 8 + qd;
            pa[0] = __float_as_uint(Ps[qr0 * ASTR + pc]);
            pa[1] = __float_as_uint(Ps[qr1 * ASTR + pc]);
            pa[2] = __float_as_uint(Ps[qr0 * ASTR + pc + 4]);
            pa[3] = __float_as_uint(Ps[qr1 * ASTR + pc + 4]);
            const float* v0 = &Vs[(ks * 8 + qd) * ASTR + grp];
            const float* v1 = &Vs[(ks * 8 + qd + 4) * ASTR + grp];
#pragma unroll
            for (int nt = 0; nt < 8; nt++) {
                mma_tf32(o[nt], pa,
                         __float_as_uint(v0[nt * 8]), __float_as_uint(v1[nt * 8]));
            }
        }
        __syncwarp();
    }

    // ---- epilogue: normalize, tf32-round, store [S, C] head-interleaved ----
    const float i0 = 1.f / l0, i1 = 1.f / l1;
#pragma unroll
    for (int nt = 0; nt < 8; nt++) {
        float2 r0v = make_float2(rna_tf32(o[nt][0] * i0), rna_tf32(o[nt][1] * i0));
        *(float2*)(out + (size_t)(qbase + qr0) * C_DIM + h * HD + nt * 8 + qd * 2) = r0v;
        float2 r1v = make_float2(rna_tf32(o[nt][2] * i1), rna_tf32(o[nt][3] * i1));
        *(float2*)(out + (size_t)(qbase + qr1) * C_DIM + h * HD + nt * 8 + qd * 2) = r1v;
    }
}

// ---------------------------------------------------------------------------
// Launch
// ---------------------------------------------------------------------------
extern "C" void kernel_launch(void* const* d_in, const int* in_sizes, int n_in,
                              void* d_out, int out_size)
{
    const float* x      = (const float*)d_in[0];
    // d_in[1] = attention_mask: exact causal triu -> handled analytically
    const float* W_attn = (const float*)d_in[2];
    const float* b_attn = (const float*)d_in[3];
    const float* W_proj = (const float*)d_in[4];
    const float* b_proj = (const float*)d_in[5];
    float* out = (float*)d_out;

    float *qkv_p, *att_p, *xt_p, *wt_p, *wpt_p;
    cudaGetSymbolAddress((void**)&qkv_p, g_qkv);
    cudaGetSymbolAddress((void**)&att_p, g_att);
    cudaGetSymbolAddress((void**)&xt_p,  g_xt);
    cudaGetSymbolAddress((void**)&wt_p,  g_wt);
    cudaGetSymbolAddress((void**)&wpt_p, g_wpt);

    // 0) tf32 rounding / transposes
    {
        int n4 = (S_LEN * C_DIM) / 4;
        cvt_tf32_kernel<<<(n4 + 255) / 256, 256>>>(
            (const float4*)x, (float4*)xt_p, n4);

        dim3 g1(3 * C_DIM / 32, C_DIM / 32);
        transpose_cvt_kernel<<<g1, 256>>>(W_attn, wt_p, C_DIM, 3 * C_DIM);

        dim3 g2(C_DIM / 32, C_DIM / 32);
        transpose_cvt_kernel<<<g2, 256>>>(W_proj, wpt_p, C_DIM, C_DIM);
    }

    cudaFuncSetAttribute(gemm_tf32_kernel,
                         cudaFuncAttributeMaxDynamicSharedMemorySize, GSMEM_DYN);

    // 1) qkv = x @ W_attn + b_attn
    {
        dim3 grid((3 * C_DIM) / GBN, S_LEN / GBM);
        gemm_tf32_kernel<<<grid, 256, GSMEM_DYN>>>(
            S_LEN, 3 * C_DIM, C_DIM, xt_p, wt_p, b_attn, qkv_p);
    }

    // 2) causal flash attention (tensor-core)
    {
        const int smem_bytes = 3 * AQ * ASTR * sizeof(float);  // 52224
        cudaFuncSetAttribute(attn_mma_kernel,
                             cudaFuncAttributeMaxDynamicSharedMemorySize, smem_bytes);
        dim3 grid(S_LEN / AQ, H_NUM);
        attn_mma_kernel<<<grid, 128, smem_bytes>>>(qkv_p, att_p);
    }

    // 3) out = att @ W_proj + b_proj
    {
        dim3 grid(C_DIM / GBN, S_LEN / GBM);
        gemm_tf32_kernel<<<grid, 256, GSMEM_DYN>>>(
            S_LEN, C_DIM, C_DIM, att_p, wpt_p, b_proj, out);
    }
}

// round 5
// speedup vs baseline: 3.4819x; 1.6388x over previous
#include <cuda_runtime.h>
#include <cuda_bf16.h>
#include <cstdint>
#include <math.h>

#define S_LEN 4096
#define C_DIM 1024
#define H_NUM 16
#define HD    64
#define KBC   (C_DIM / 8)      // 128 k-blocks for K=1024

// Scratch (__device__ globals: allocation-free rule)
__device__ float g_qkv[(size_t)S_LEN * 3 * C_DIM];   // row-major [S][3C], tf32-rounded, Q pre-scaled
__device__ float g_att[(size_t)S_LEN * C_DIM];       // A-perm layout for proj GEMM
__device__ float g_xp [(size_t)S_LEN * C_DIM];       // x in A-perm layout
__device__ float g_wtp[(size_t)3 * C_DIM * C_DIM];   // W_attn in B-perm (Q cols pre-scaled)
__device__ float g_wpp[(size_t)C_DIM * C_DIM];       // W_proj in B-perm
__device__ float g_ba [3 * C_DIM];                   // b_attn with Q part pre-scaled

// ---------------------------------------------------------------------------
// Helpers
// ---------------------------------------------------------------------------
__device__ __forceinline__ float rna_tf32(float x) {
    uint32_t t;
    asm("cvt.rna.tf32.f32 %0, %1;" : "=r"(t) : "f"(x));
    return __uint_as_float(t);
}

__device__ __forceinline__ void cp16(void* s, const float* g) {
    uint32_t sa = (uint32_t)__cvta_generic_to_shared(s);
    asm volatile("cp.async.cg.shared.global [%0], [%1], 16;"
                 :: "r"(sa), "l"(__cvta_generic_to_global(g)));
}

// m16n8k8 tf32 mma. A row-major, B col-major.
// A frag: a0=(g,q) a1=(g+8,q) a2=(g,q+4) a3=(g+8,q+4)   [g=lane>>2, q=lane&3]
// B frag: b0=(k=q,n=g) b1=(k=q+4,n=g)
// C frag: c0=(g,2q) c1=(g,2q+1) c2=(g+8,2q) c3=(g+8,2q+1)
__device__ __forceinline__ void mma_tf32(float c[4], const uint32_t a[4],
                                         uint32_t b0, uint32_t b1) {
    asm volatile(
        "mma.sync.aligned.m16n8k8.row.col.f32.tf32.tf32.f32 "
        "{%0,%1,%2,%3}, {%4,%5,%6,%7}, {%8,%9}, {%0,%1,%2,%3};"
        : "+f"(c[0]), "+f"(c[1]), "+f"(c[2]), "+f"(c[3])
        : "r"(a[0]), "r"(a[1]), "r"(a[2]), "r"(a[3]), "r"(b0), "r"(b1));
}

// ---------------------------------------------------------------------------
// Prep: A-perm of x. Layout: [mb][kb][lane][4] with
//   lane=g*4+q, vals {(g,q),(g+8,q),(g,q+4),(g+8,q+4)} within 16x8 block.
// ---------------------------------------------------------------------------
__global__ __launch_bounds__(256) void permA_kernel(
    const float* __restrict__ in, float* __restrict__ out, int M, int K)
{
    int cid = blockIdx.x * 256 + threadIdx.x;
    if (cid >= (M * K) / 4) return;
    const int per_mb = (K >> 3) * 32;
    int mb  = cid / per_mb;
    int rem = cid - mb * per_mb;
    int kb  = rem >> 5;
    int lane = rem & 31;
    int g = lane >> 2, q = lane & 3;
    size_t r = mb * 16 + g, c = kb * 8 + q;
    float4 o;
    o.x = rna_tf32(in[r * K + c]);
    o.y = rna_tf32(in[(r + 8) * K + c]);
    o.z = rna_tf32(in[r * K + c + 4]);
    o.w = rna_tf32(in[(r + 8) * K + c + 4]);
    ((float4*)out)[cid] = o;
}

// ---------------------------------------------------------------------------
// Prep: B-perm of W [K][N] -> [nb][kb][lane][2], vals {W[k=q][n=g], W[k=q+4][n=g]}
// Columns n < scaleN get *0.125 (Q scale folding).
// ---------------------------------------------------------------------------
__global__ __launch_bounds__(256) void permB_kernel(
    const float* __restrict__ W, float* __restrict__ out,
    int K, int N, int scaleN)
{
    int cid = blockIdx.x * 256 + threadIdx.x;
    if (cid >= (N * K) / 2) return;
    const int per_nb = (K >> 3) * 32;
    int nb  = cid / per_nb;
    int rem = cid - nb * per_nb;
    int kb  = rem >> 5;
    int lane = rem & 31;
    int g = lane >> 2, q = lane & 3;
    size_t n = nb * 8 + g, k = kb * 8 + q;
    float s = (n < (size_t)scaleN) ? 0.125f : 1.f;
    float2 o;
    o.x = rna_tf32(W[k * N + n] * s);
    o.y = rna_tf32(W[(k + 4) * N + n] * s);
    ((float2*)out)[cid] = o;
}

__global__ __launch_bounds__(256) void bias_prep_kernel(
    const float* __restrict__ b, float* __restrict__ o, int n, int scaleN)
{
    int i = blockIdx.x * 256 + threadIdx.x;
    if (i < n) o[i] = b[i] * (i < scaleN ? 0.125f : 1.f);
}

// ---------------------------------------------------------------------------
// tf32 mma.sync GEMM on permuted operands.
//   C[M,N] = A[M,K] @ B^T + bias,  A in A-perm, B in B-perm.
// CTA 128x128, BK=32, 3-stage cp.async, 8 warps (2m x 4n), warp tile 64x32.
// ROUND: tf32-round outputs (for qkv feeding attention).
// ---------------------------------------------------------------------------
#define GSTAGE_F 8192                  // floats per stage: A 4096 + B 4096
#define GSMEM_DYN (3 * GSTAGE_F * 4)   // 98304 B

extern __shared__ float gsm[];

template<bool ROUND>
__global__ __launch_bounds__(256, 2) void gemm_mma_kernel(
    int M, int N, int K,
    const float* __restrict__ Ap,
    const float* __restrict__ Bp,
    const float* __restrict__ bias,
    float* __restrict__ C)
{
    const int tid  = threadIdx.x;
    const int wid  = tid >> 5;
    const int lane = tid & 31;
    const int g    = lane >> 2, q = lane & 3;
    const int bm   = blockIdx.y * 128;
    const int bn   = blockIdx.x * 128;
    const int mb0  = (wid >> 2) * 4;    // m-block offset within tile (4 blocks)
    const int nb0  = (wid & 3) * 4;     // n-block offset within tile (4 blocks)
    const int KB   = K >> 3;
    const int nch  = K >> 5;

    float acc[4][4][4];
#pragma unroll
    for (int i = 0; i < 4; i++)
#pragma unroll
        for (int j = 0; j < 4; j++)
#pragma unroll
            for (int e = 0; e < 4; e++) acc[i][j][e] = 0.f;

    auto load_stage = [&](int s, int ch) {
        float* As = gsm + s * GSTAGE_F;
        float* Bs = As + 4096;
        const int kb0 = ch * 4;
#pragma unroll
        for (int it = 0; it < 4; it++) {               // A: 8 mb x 512 floats
            int idx = tid + it * 256;
            int mb = idx >> 7, off = idx & 127;
            const float* src = Ap +
                ((size_t)((bm >> 4) + mb) * KB + kb0) * 128 + off * 4;
            cp16(As + mb * 512 + off * 4, src);
        }
#pragma unroll
        for (int it = 0; it < 4; it++) {               // B: 16 nb x 256 floats
            int idx = tid + it * 256;
            int nb = idx >> 6, off = idx & 63;
            const float* src = Bp +
                ((size_t)((bn >> 3) + nb) * KB + kb0) * 64 + off * 4;
            cp16(Bs + nb * 256 + off * 4, src);
        }
        asm volatile("cp.async.commit_group;" ::: "memory");
    };

    load_stage(0, 0);
    load_stage(1, 1);

    for (int ch = 0; ch < nch; ch++) {
        if (ch + 2 < nch)
            asm volatile("cp.async.wait_group 1;" ::: "memory");
        else
            asm volatile("cp.async.wait_group 0;" ::: "memory");
        __syncthreads();

        if (ch + 2 < nch) load_stage((ch + 2) % 3, ch + 2);

        const float* As = gsm + (ch % 3) * GSTAGE_F;
        const float* Bs = As + 4096;

#pragma unroll
        for (int ks = 0; ks < 4; ks++) {
            float4 afr[4];
            float2 bfr[4];
#pragma unroll
            for (int i = 0; i < 4; i++)
                afr[i] = *(const float4*)(As + ((mb0 + i) * 4 + ks) * 128 + lane * 4);
#pragma unroll
            for (int j = 0; j < 4; j++)
                bfr[j] = *(const float2*)(Bs + ((nb0 + j) * 4 + ks) * 64 + lane * 2);
#pragma unroll
            for (int i = 0; i < 4; i++)
#pragma unroll
                for (int j = 0; j < 4; j++)
                    mma_tf32(acc[i][j], (const uint32_t*)&afr[i],
                             __float_as_uint(bfr[j].x), __float_as_uint(bfr[j].y));
        }
    }

    // Epilogue: direct gmem float2 stores + bias (+ optional rounding)
#pragma unroll
    for (int j = 0; j < 4; j++) {
        const int col = bn + (wid & 3) * 32 + j * 8 + 2 * q;
        const float2 bv = *(const float2*)(bias + col);
#pragma unroll
        for (int i = 0; i < 4; i++) {
            const int r0 = bm + (wid >> 2) * 64 + i * 16 + g;
            float2 o0, o1;
            o0.x = acc[i][j][0] + bv.x;
            o0.y = acc[i][j][1] + bv.y;
            o1.x = acc[i][j][2] + bv.x;
            o1.y = acc[i][j][3] + bv.y;
            if (ROUND) {
                o0.x = rna_tf32(o0.x); o0.y = rna_tf32(o0.y);
                o1.x = rna_tf32(o1.x); o1.y = rna_tf32(o1.y);
            }
            *(float2*)(C + (size_t)r0 * N + col) = o0;
            *(float2*)(C + (size_t)(r0 + 8) * N + col) = o1;
        }
    }
}

// ---------------------------------------------------------------------------
// Causal flash attention, mma.sync tf32, double-buffered cp.async K/V.
// qkv is pre-rounded; Q pre-scaled (W/b folding). Output -> g_att in A-perm.
// CTA = (head, 64-q-tile), 128 threads. K pad 68, V pad 72 (conflict-free).
// ---------------------------------------------------------------------------
#define KSTR 68
#define VSTR 72
#define PSTR 68
#define ASTAGE_F (64 * KSTR + 64 * VSTR)   // 8960 floats
#define ASMEM_DYN ((2 * ASTAGE_F + 64 * PSTR) * 4)   // 89088 B

extern __shared__ float asmem[];

__global__ __launch_bounds__(128) void attn_mma_kernel(
    const float* __restrict__ qkv, float* __restrict__ att)
{
    float* Ps = asmem + 2 * ASTAGE_F;

    const int tid   = threadIdx.x;
    const int warp  = tid >> 5;
    const int lane  = tid & 31;
    const int grp   = lane >> 2;
    const int qd    = lane & 3;
    const int h     = blockIdx.y;
    const int qtile = gridDim.x - 1 - blockIdx.x;   // big tiles first
    const int qbase = qtile * 64;
    const int qr0   = warp * 16 + grp;
    const int qr1   = qr0 + 8;

    // ---- Q fragments: direct gmem loads (pre-rounded, pre-scaled) ----
    uint32_t qa[8][4];
    {
        const float* Qb = qkv + (size_t)qbase * (3 * C_DIM) + h * HD;
#pragma unroll
        for (int ks = 0; ks < 8; ks++) {
            const int c = ks * 8 + qd;
            qa[ks][0] = __float_as_uint(Qb[(size_t)qr0 * (3 * C_DIM) + c]);
            qa[ks][1] = __float_as_uint(Qb[(size_t)qr1 * (3 * C_DIM) + c]);
            qa[ks][2] = __float_as_uint(Qb[(size_t)qr0 * (3 * C_DIM) + c + 4]);
            qa[ks][3] = __float_as_uint(Qb[(size_t)qr1 * (3 * C_DIM) + c + 4]);
        }
    }

    auto load_kv = [&](int s, int jt) {
        float* Ks = asmem + s * ASTAGE_F;
        float* Vs = Ks + 64 * KSTR;
        const int kvbase = jt * 64;
#pragma unroll
        for (int it = 0; it < 8; it++) {
            int idx = tid + it * 128;
            int r = idx >> 4, d4 = (idx & 15) * 4;
            const float* base = qkv + (size_t)(kvbase + r) * (3 * C_DIM) + h * HD + d4;
            cp16(Ks + r * KSTR + d4, base + C_DIM);
            cp16(Vs + r * VSTR + d4, base + 2 * C_DIM);
        }
        asm volatile("cp.async.commit_group;" ::: "memory");
    };

    load_kv(0, 0);

    float o[8][4];
#pragma unroll
    for (int nt = 0; nt < 8; nt++)
#pragma unroll
        for (int e = 0; e < 4; e++) o[nt][e] = 0.f;
    float m0 = -INFINITY, m1 = -INFINITY, l0 = 0.f, l1 = 0.f;

    for (int jt = 0; jt <= qtile; jt++) {
        const int s = jt & 1;
        if (jt) __syncthreads();          // all warps done with stage being overwritten
        if (jt < qtile) load_kv(s ^ 1, jt + 1);
        if (jt < qtile)
            asm volatile("cp.async.wait_group 1;" ::: "memory");
        else
            asm volatile("cp.async.wait_group 0;" ::: "memory");
        __syncthreads();

        const float* Ks = asmem + s * ASTAGE_F;
        const float* Vs = Ks + 64 * KSTR;
        const int kvbase = jt * 64;

        // ---- S = Q K^T ----
        float sv[8][4];
#pragma unroll
        for (int nt = 0; nt < 8; nt++)
#pragma unroll
            for (int e = 0; e < 4; e++) sv[nt][e] = 0.f;

#pragma unroll
        for (int ks = 0; ks < 8; ks++) {
            const int kc = ks * 8 + qd;
#pragma unroll
            for (int nt = 0; nt < 8; nt++) {
                const float* kr = &Ks[(nt * 8 + grp) * KSTR + kc];
                mma_tf32(sv[nt], qa[ks],
                         __float_as_uint(kr[0]), __float_as_uint(kr[4]));
            }
        }

        // ---- causal mask on diagonal tile ----
        if (jt == qtile) {
            const int rg0 = qbase + qr0, rg1 = qbase + qr1;
#pragma unroll
            for (int nt = 0; nt < 8; nt++) {
                int cg = kvbase + nt * 8 + qd * 2;
                if (cg     > rg0) sv[nt][0] = -INFINITY;
                if (cg + 1 > rg0) sv[nt][1] = -INFINITY;
                if (cg     > rg1) sv[nt][2] = -INFINITY;
                if (cg + 1 > rg1) sv[nt][3] = -INFINITY;
            }
        }

        // ---- online softmax ----
        float mt0 = -INFINITY, mt1 = -INFINITY;
#pragma unroll
        for (int nt = 0; nt < 8; nt++) {
            mt0 = fmaxf(mt0, fmaxf(sv[nt][0], sv[nt][1]));
            mt1 = fmaxf(mt1, fmaxf(sv[nt][2], sv[nt][3]));
        }
        mt0 = fmaxf(mt0, __shfl_xor_sync(0xffffffffu, mt0, 1));
        mt0 = fmaxf(mt0, __shfl_xor_sync(0xffffffffu, mt0, 2));
        mt1 = fmaxf(mt1, __shfl_xor_sync(0xffffffffu, mt1, 1));
        mt1 = fmaxf(mt1, __shfl_xor_sync(0xffffffffu, mt1, 2));

        const float mn0 = fmaxf(m0, mt0), mn1 = fmaxf(m1, mt1);
        const float al0 = __expf(m0 - mn0), al1 = __expf(m1 - mn1);
        m0 = mn0; m1 = mn1;

        float rs0 = 0.f, rs1 = 0.f;
#pragma unroll
        for (int nt = 0; nt < 8; nt++) {
            sv[nt][0] = __expf(sv[nt][0] - mn0);
            sv[nt][1] = __expf(sv[nt][1] - mn0);
            sv[nt][2] = __expf(sv[nt][2] - mn1);
            sv[nt][3] = __expf(sv[nt][3] - mn1);
            rs0 += sv[nt][0] + sv[nt][1];
            rs1 += sv[nt][2] + sv[nt][3];
        }
        rs0 += __shfl_xor_sync(0xffffffffu, rs0, 1);
        rs0 += __shfl_xor_sync(0xffffffffu, rs0, 2);
        rs1 += __shfl_xor_sync(0xffffffffu, rs1, 1);
        rs1 += __shfl_xor_sync(0xffffffffu, rs1, 2);
        l0 = l0 * al0 + rs0;
        l1 = l1 * al1 + rs1;

#pragma unroll
        for (int nt = 0; nt < 8; nt++) {
            o[nt][0] *= al0; o[nt][1] *= al0;
            o[nt][2] *= al1; o[nt][3] *= al1;
        }

        // ---- P -> warp-private smem (tf32-rounded) ----
#pragma unroll
        for (int nt = 0; nt < 8; nt++) {
            float2 p0 = make_float2(rna_tf32(sv[nt][0]), rna_tf32(sv[nt][1]));
            *(float2*)(&Ps[qr0 * PSTR + nt * 8 + qd * 2]) = p0;
            float2 p1 = make_float2(rna_tf32(sv[nt][2]), rna_tf32(sv[nt][3]));
            *(float2*)(&Ps[qr1 * PSTR + nt * 8 + qd * 2]) = p1;
        }
        __syncwarp();

        // ---- O += P V ----
#pragma unroll
        for (int ks = 0; ks < 8; ks++) {
            uint32_t pa[4];
            const int pc = ks * 8 + qd;
            pa[0] = __float_as_uint(Ps[qr0 * PSTR + pc]);
            pa[1] = __float_as_uint(Ps[qr1 * PSTR + pc]);
            pa[2] = __float_as_uint(Ps[qr0 * PSTR + pc + 4]);
            pa[3] = __float_as_uint(Ps[qr1 * PSTR + pc + 4]);
            const float* v0 = &Vs[(ks * 8 + qd) * VSTR + grp];
            const float* v1 = &Vs[(ks * 8 + qd + 4) * VSTR + grp];
#pragma unroll
            for (int nt = 0; nt < 8; nt++)
                mma_tf32(o[nt], pa,
                         __float_as_uint(v0[nt * 8]), __float_as_uint(v1[nt * 8]));
        }
        __syncwarp();
    }

    // ---- epilogue: normalize + tf32-round, store g_att in A-perm layout ----
    const float i0 = 1.f / l0, i1 = 1.f / l1;
    const int mbq = qtile * 4 + warp;      // (qbase+qr0)>>4 ; row&15 = grp, qr1 sets bit3
#pragma unroll
    for (int nt = 0; nt < 8; nt++) {
        const int kb = h * 8 + nt;
        float* blk = att + ((size_t)mbq * KBC + kb) * 128;
#pragma unroll
        for (int e = 0; e < 2; e++) {
            const int cb = 2 * qd + e;
            const int lane2 = grp * 4 + (cb & 3);
            const int jhi = ((cb >> 2) & 1) * 2;
            blk[lane2 * 4 + jhi]     = rna_tf32(o[nt][e]     * i0);
            blk[lane2 * 4 + jhi + 1] = rna_tf32(o[nt][2 + e] * i1);
        }
    }
}

// ---------------------------------------------------------------------------
// Launch
// ---------------------------------------------------------------------------
extern "C" void kernel_launch(void* const* d_in, const int* in_sizes, int n_in,
                              void* d_out, int out_size)
{
    const float* x      = (const float*)d_in[0];
    // d_in[1] = attention_mask: exact causal triu -> handled analytically
    const float* W_attn = (const float*)d_in[2];
    const float* b_attn = (const float*)d_in[3];
    const float* W_proj = (const float*)d_in[4];
    const float* b_proj = (const float*)d_in[5];
    float* out = (float*)d_out;

    float *qkv_p, *att_p, *xp_p, *wtp_p, *wpp_p, *ba_p;
    cudaGetSymbolAddress((void**)&qkv_p, g_qkv);
    cudaGetSymbolAddress((void**)&att_p, g_att);
    cudaGetSymbolAddress((void**)&xp_p,  g_xp);
    cudaGetSymbolAddress((void**)&wtp_p, g_wtp);
    cudaGetSymbolAddress((void**)&wpp_p, g_wpp);
    cudaGetSymbolAddress((void**)&ba_p,  g_ba);

    // 0) prep: permute + tf32-round operands; fold 0.125 into W_attn Q cols + b_attn
    {
        int nA = (S_LEN * C_DIM) / 4;
        permA_kernel<<<(nA + 255) / 256, 256>>>(x, xp_p, S_LEN, C_DIM);

        int nB1 = (3 * C_DIM * C_DIM) / 2;
        permB_kernel<<<(nB1 + 255) / 256, 256>>>(W_attn, wtp_p, C_DIM, 3 * C_DIM, C_DIM);

        int nB2 = (C_DIM * C_DIM) / 2;
        permB_kernel<<<(nB2 + 255) / 256, 256>>>(W_proj, wpp_p, C_DIM, C_DIM, 0);

        bias_prep_kernel<<<(3 * C_DIM + 255) / 256, 256>>>(b_attn, ba_p, 3 * C_DIM, C_DIM);
    }

    cudaFuncSetAttribute(gemm_mma_kernel<true>,
                         cudaFuncAttributeMaxDynamicSharedMemorySize, GSMEM_DYN);
    cudaFuncSetAttribute(gemm_mma_kernel<false>,
                         cudaFuncAttributeMaxDynamicSharedMemorySize, GSMEM_DYN);

    // 1) qkv = x @ W_attn + b_attn  (rounded output, Q pre-scaled)
    {
        dim3 grid((3 * C_DIM) / 128, S_LEN / 128);
        gemm_mma_kernel<true><<<grid, 256, GSMEM_DYN>>>(
            S_LEN, 3 * C_DIM, C_DIM, xp_p, wtp_p, ba_p, qkv_p);
    }

    // 2) causal flash attention (tensor-core, double-buffered cp.async)
    {
        cudaFuncSetAttribute(attn_mma_kernel,
                             cudaFuncAttributeMaxDynamicSharedMemorySize, ASMEM_DYN);
        dim3 grid(S_LEN / 64, H_NUM);
        attn_mma_kernel<<<grid, 128, ASMEM_DYN>>>(qkv_p, att_p);
    }

    // 3) out = att @ W_proj + b_proj
    {
        dim3 grid(C_DIM / 128, S_LEN / 128);
        gemm_mma_kernel<false><<<grid, 256, GSMEM_DYN>>>(
            S_LEN, C_DIM, C_DIM, att_p, wpp_p, b_proj, out);
    }
}

// round 6
// speedup vs baseline: 3.5807x; 1.0284x over previous
#include <cuda_runtime.h>
#include <cuda_bf16.h>
#include <cstdint>
#include <math.h>

#define S_LEN 4096
#define C_DIM 1024
#define H_NUM 16
#define HD    64
#define KBC   (C_DIM / 8)      // 128 k-blocks for K=1024

// Scratch (__device__ globals: allocation-free rule)
__device__ float g_qkv[(size_t)S_LEN * 3 * C_DIM];   // row-major [S][3C], tf32-rounded, Q pre-scaled
__device__ float g_att[(size_t)S_LEN * C_DIM];       // A-perm layout for proj GEMM
__device__ float g_xp [(size_t)S_LEN * C_DIM];       // x in A-perm layout
__device__ float g_wtp[(size_t)3 * C_DIM * C_DIM];   // W_attn in B-perm (Q cols pre-scaled)
__device__ float g_wpp[(size_t)C_DIM * C_DIM];       // W_proj in B-perm
__device__ float g_ba [3 * C_DIM];                   // b_attn with Q part pre-scaled

// ---------------------------------------------------------------------------
// Helpers
// ---------------------------------------------------------------------------
__device__ __forceinline__ float rna_tf32(float x) {
    uint32_t t;
    asm("cvt.rna.tf32.f32 %0, %1;" : "=r"(t) : "f"(x));
    return __uint_as_float(t);
}

__device__ __forceinline__ void cp16(void* s, const float* g) {
    uint32_t sa = (uint32_t)__cvta_generic_to_shared(s);
    asm volatile("cp.async.cg.shared.global [%0], [%1], 16;"
                 :: "r"(sa), "l"(__cvta_generic_to_global(g)));
}

// m16n8k8 tf32 mma. A row-major, B col-major.
// A frag: a0=(g,q) a1=(g+8,q) a2=(g,q+4) a3=(g+8,q+4)   [g=lane>>2, q=lane&3]
// B frag: b0=(k=q,n=g) b1=(k=q+4,n=g)
// C frag: c0=(g,2q) c1=(g,2q+1) c2=(g+8,2q) c3=(g+8,2q+1)
__device__ __forceinline__ void mma_tf32(float c[4], const uint32_t a[4],
                                         uint32_t b0, uint32_t b1) {
    asm volatile(
        "mma.sync.aligned.m16n8k8.row.col.f32.tf32.tf32.f32 "
        "{%0,%1,%2,%3}, {%4,%5,%6,%7}, {%8,%9}, {%0,%1,%2,%3};"
        : "+f"(c[0]), "+f"(c[1]), "+f"(c[2]), "+f"(c[3])
        : "r"(a[0]), "r"(a[1]), "r"(a[2]), "r"(a[3]), "r"(b0), "r"(b1));
}

// ---------------------------------------------------------------------------
// Prep: A-perm of x. Layout: [mb][kb][lane][4]
// ---------------------------------------------------------------------------
__global__ __launch_bounds__(256) void permA_kernel(
    const float* __restrict__ in, float* __restrict__ out, int M, int K)
{
    int cid = blockIdx.x * 256 + threadIdx.x;
    if (cid >= (M * K) / 4) return;
    const int per_mb = (K >> 3) * 32;
    int mb  = cid / per_mb;
    int rem = cid - mb * per_mb;
    int kb  = rem >> 5;
    int lane = rem & 31;
    int g = lane >> 2, q = lane & 3;
    size_t r = mb * 16 + g, c = kb * 8 + q;
    float4 o;
    o.x = rna_tf32(in[r * K + c]);
    o.y = rna_tf32(in[(r + 8) * K + c]);
    o.z = rna_tf32(in[r * K + c + 4]);
    o.w = rna_tf32(in[(r + 8) * K + c + 4]);
    ((float4*)out)[cid] = o;
}

// ---------------------------------------------------------------------------
// Prep: B-perm of W [K][N] -> [nb][kb][lane][2]; cols n<scaleN get *0.125
// ---------------------------------------------------------------------------
__global__ __launch_bounds__(256) void permB_kernel(
    const float* __restrict__ W, float* __restrict__ out,
    int K, int N, int scaleN)
{
    int cid = blockIdx.x * 256 + threadIdx.x;
    if (cid >= (N * K) / 2) return;
    const int per_nb = (K >> 3) * 32;
    int nb  = cid / per_nb;
    int rem = cid - nb * per_nb;
    int kb  = rem >> 5;
    int lane = rem & 31;
    int g = lane >> 2, q = lane & 3;
    size_t n = nb * 8 + g, k = kb * 8 + q;
    float s = (n < (size_t)scaleN) ? 0.125f : 1.f;
    float2 o;
    o.x = rna_tf32(W[k * N + n] * s);
    o.y = rna_tf32(W[(k + 4) * N + n] * s);
    ((float2*)out)[cid] = o;
}

__global__ __launch_bounds__(256) void bias_prep_kernel(
    const float* __restrict__ b, float* __restrict__ o, int n, int scaleN)
{
    int i = blockIdx.x * 256 + threadIdx.x;
    if (i < n) o[i] = b[i] * (i < scaleN ? 0.125f : 1.f);
}

// ---------------------------------------------------------------------------
// tf32 mma.sync GEMM on permuted operands (unchanged from round 5).
// ---------------------------------------------------------------------------
#define GSTAGE_F 8192
#define GSMEM_DYN (3 * GSTAGE_F * 4)

extern __shared__ float gsm[];

template<bool ROUND>
__global__ __launch_bounds__(256, 2) void gemm_mma_kernel(
    int M, int N, int K,
    const float* __restrict__ Ap,
    const float* __restrict__ Bp,
    const float* __restrict__ bias,
    float* __restrict__ C)
{
    const int tid  = threadIdx.x;
    const int wid  = tid >> 5;
    const int lane = tid & 31;
    const int g    = lane >> 2, q = lane & 3;
    const int bm   = blockIdx.y * 128;
    const int bn   = blockIdx.x * 128;
    const int mb0  = (wid >> 2) * 4;
    const int nb0  = (wid & 3) * 4;
    const int KB   = K >> 3;
    const int nch  = K >> 5;

    float acc[4][4][4];
#pragma unroll
    for (int i = 0; i < 4; i++)
#pragma unroll
        for (int j = 0; j < 4; j++)
#pragma unroll
            for (int e = 0; e < 4; e++) acc[i][j][e] = 0.f;

    auto load_stage = [&](int s, int ch) {
        float* As = gsm + s * GSTAGE_F;
        float* Bs = As + 4096;
        const int kb0 = ch * 4;
#pragma unroll
        for (int it = 0; it < 4; it++) {
            int idx = tid + it * 256;
            int mb = idx >> 7, off = idx & 127;
            const float* src = Ap +
                ((size_t)((bm >> 4) + mb) * KB + kb0) * 128 + off * 4;
            cp16(As + mb * 512 + off * 4, src);
        }
#pragma unroll
        for (int it = 0; it < 4; it++) {
            int idx = tid + it * 256;
            int nb = idx >> 6, off = idx & 63;
            const float* src = Bp +
                ((size_t)((bn >> 3) + nb) * KB + kb0) * 64 + off * 4;
            cp16(Bs + nb * 256 + off * 4, src);
        }
        asm volatile("cp.async.commit_group;" ::: "memory");
    };

    load_stage(0, 0);
    load_stage(1, 1);

    for (int ch = 0; ch < nch; ch++) {
        if (ch + 2 < nch)
            asm volatile("cp.async.wait_group 1;" ::: "memory");
        else
            asm volatile("cp.async.wait_group 0;" ::: "memory");
        __syncthreads();

        if (ch + 2 < nch) load_stage((ch + 2) % 3, ch + 2);

        const float* As = gsm + (ch % 3) * GSTAGE_F;
        const float* Bs = As + 4096;

#pragma unroll
        for (int ks = 0; ks < 4; ks++) {
            float4 afr[4];
            float2 bfr[4];
#pragma unroll
            for (int i = 0; i < 4; i++)
                afr[i] = *(const float4*)(As + ((mb0 + i) * 4 + ks) * 128 + lane * 4);
#pragma unroll
            for (int j = 0; j < 4; j++)
                bfr[j] = *(const float2*)(Bs + ((nb0 + j) * 4 + ks) * 64 + lane * 2);
#pragma unroll
            for (int i = 0; i < 4; i++)
#pragma unroll
                for (int j = 0; j < 4; j++)
                    mma_tf32(acc[i][j], (const uint32_t*)&afr[i],
                             __float_as_uint(bfr[j].x), __float_as_uint(bfr[j].y));
        }
    }

#pragma unroll
    for (int j = 0; j < 4; j++) {
        const int col = bn + (wid & 3) * 32 + j * 8 + 2 * q;
        const float2 bv = *(const float2*)(bias + col);
#pragma unroll
        for (int i = 0; i < 4; i++) {
            const int r0 = bm + (wid >> 2) * 64 + i * 16 + g;
            float2 o0, o1;
            o0.x = acc[i][j][0] + bv.x;
            o0.y = acc[i][j][1] + bv.y;
            o1.x = acc[i][j][2] + bv.x;
            o1.y = acc[i][j][3] + bv.y;
            if (ROUND) {
                o0.x = rna_tf32(o0.x); o0.y = rna_tf32(o0.y);
                o1.x = rna_tf32(o1.x); o1.y = rna_tf32(o1.y);
            }
            *(float2*)(C + (size_t)r0 * N + col) = o0;
            *(float2*)(C + (size_t)(r0 + 8) * N + col) = o1;
        }
    }
}

// ---------------------------------------------------------------------------
// Causal flash attention, mma.sync tf32.
// CTA = (head, 128-q-row tile), 256 threads = 8 warps x 16-row strips.
// kv tiles of 64, double-buffered cp.async. Warps 0-3 skip the final
// (fully future-masked) kv tile. Output -> g_att in A-perm layout.
// ---------------------------------------------------------------------------
#define KSTR 68
#define VSTR 72
#define PSTR 68
#define ASTAGE_F (64 * KSTR + 64 * VSTR)                 // 8960 floats
#define ASMEM_DYN ((2 * ASTAGE_F + 128 * PSTR) * 4)      // 106496 B

extern __shared__ float asmem[];

__global__ __launch_bounds__(256) void attn_mma_kernel(
    const float* __restrict__ qkv, float* __restrict__ att)
{
    float* Ps = asmem + 2 * ASTAGE_F;

    const int tid   = threadIdx.x;
    const int warp  = tid >> 5;
    const int lane  = tid & 31;
    const int grp   = lane >> 2;
    const int qd    = lane & 3;
    const int h     = blockIdx.y;
    const int qtile = gridDim.x - 1 - blockIdx.x;   // big tiles first
    const int qbase = qtile * 128;
    const int qr0   = warp * 16 + grp;              // 0..127
    const int qr1   = qr0 + 8;
    const int njt   = 2 * qtile + 2;                // kv tiles of 64

    // ---- Q fragments: direct gmem loads (pre-rounded, pre-scaled) ----
    uint32_t qa[8][4];
    {
        const float* Qb = qkv + (size_t)qbase * (3 * C_DIM) + h * HD;
#pragma unroll
        for (int ks = 0; ks < 8; ks++) {
            const int c = ks * 8 + qd;
            qa[ks][0] = __float_as_uint(Qb[(size_t)qr0 * (3 * C_DIM) + c]);
            qa[ks][1] = __float_as_uint(Qb[(size_t)qr1 * (3 * C_DIM) + c]);
            qa[ks][2] = __float_as_uint(Qb[(size_t)qr0 * (3 * C_DIM) + c + 4]);
            qa[ks][3] = __float_as_uint(Qb[(size_t)qr1 * (3 * C_DIM) + c + 4]);
        }
    }

    auto load_kv = [&](int s, int jt) {
        float* Ks = asmem + s * ASTAGE_F;
        float* Vs = Ks + 64 * KSTR;
        const int kvbase = jt * 64;
#pragma unroll
        for (int it = 0; it < 4; it++) {
            int idx = tid + it * 256;
            int r = idx >> 4, d4 = (idx & 15) * 4;
            const float* base = qkv + (size_t)(kvbase + r) * (3 * C_DIM) + h * HD + d4;
            cp16(Ks + r * KSTR + d4, base + C_DIM);
            cp16(Vs + r * VSTR + d4, base + 2 * C_DIM);
        }
        asm volatile("cp.async.commit_group;" ::: "memory");
    };

    load_kv(0, 0);

    float o[8][4];
#pragma unroll
    for (int nt = 0; nt < 8; nt++)
#pragma unroll
        for (int e = 0; e < 4; e++) o[nt][e] = 0.f;
    float m0 = -INFINITY, m1 = -INFINITY, l0 = 0.f, l1 = 0.f;

    for (int jt = 0; jt < njt; jt++) {
        const int s = jt & 1;
        if (jt) __syncthreads();          // everyone done with stage being reused
        if (jt + 1 < njt) load_kv(s ^ 1, jt + 1);
        if (jt + 1 < njt)
            asm volatile("cp.async.wait_group 1;" ::: "memory");
        else
            asm volatile("cp.async.wait_group 0;" ::: "memory");
        __syncthreads();

        // warps 0-3 are entirely in the future of the last kv tile -> skip
        if (warp < 4 && jt == njt - 1) continue;

        const float* Ks = asmem + s * ASTAGE_F;
        const float* Vs = Ks + 64 * KSTR;
        const int kvbase = jt * 64;

        // ---- S = Q K^T ----
        float sv[8][4];
#pragma unroll
        for (int nt = 0; nt < 8; nt++)
#pragma unroll
            for (int e = 0; e < 4; e++) sv[nt][e] = 0.f;

#pragma unroll
        for (int ks = 0; ks < 8; ks++) {
            const int kc = ks * 8 + qd;
#pragma unroll
            for (int nt = 0; nt < 8; nt++) {
                const float* kr = &Ks[(nt * 8 + grp) * KSTR + kc];
                mma_tf32(sv[nt], qa[ks],
                         __float_as_uint(kr[0]), __float_as_uint(kr[4]));
            }
        }

        // ---- causal mask (only tiles overlapping/after the diagonal) ----
        if (jt >= 2 * qtile) {
            const int rg0 = qbase + qr0, rg1 = qbase + qr1;
#pragma unroll
            for (int nt = 0; nt < 8; nt++) {
                int cg = kvbase + nt * 8 + qd * 2;
                if (cg     > rg0) sv[nt][0] = -INFINITY;
                if (cg + 1 > rg0) sv[nt][1] = -INFINITY;
                if (cg     > rg1) sv[nt][2] = -INFINITY;
                if (cg + 1 > rg1) sv[nt][3] = -INFINITY;
            }
        }

        // ---- online softmax ----
        float mt0 = -INFINITY, mt1 = -INFINITY;
#pragma unroll
        for (int nt = 0; nt < 8; nt++) {
            mt0 = fmaxf(mt0, fmaxf(sv[nt][0], sv[nt][1]));
            mt1 = fmaxf(mt1, fmaxf(sv[nt][2], sv[nt][3]));
        }
        mt0 = fmaxf(mt0, __shfl_xor_sync(0xffffffffu, mt0, 1));
        mt0 = fmaxf(mt0, __shfl_xor_sync(0xffffffffu, mt0, 2));
        mt1 = fmaxf(mt1, __shfl_xor_sync(0xffffffffu, mt1, 1));
        mt1 = fmaxf(mt1, __shfl_xor_sync(0xffffffffu, mt1, 2));

        const float mn0 = fmaxf(m0, mt0), mn1 = fmaxf(m1, mt1);
        const float al0 = __expf(m0 - mn0), al1 = __expf(m1 - mn1);
        m0 = mn0; m1 = mn1;

        float rs0 = 0.f, rs1 = 0.f;
#pragma unroll
        for (int nt = 0; nt < 8; nt++) {
            sv[nt][0] = __expf(sv[nt][0] - mn0);
            sv[nt][1] = __expf(sv[nt][1] - mn0);
            sv[nt][2] = __expf(sv[nt][2] - mn1);
            sv[nt][3] = __expf(sv[nt][3] - mn1);
            rs0 += sv[nt][0] + sv[nt][1];
            rs1 += sv[nt][2] + sv[nt][3];
        }
        rs0 += __shfl_xor_sync(0xffffffffu, rs0, 1);
        rs0 += __shfl_xor_sync(0xffffffffu, rs0, 2);
        rs1 += __shfl_xor_sync(0xffffffffu, rs1, 1);
        rs1 += __shfl_xor_sync(0xffffffffu, rs1, 2);
        l0 = l0 * al0 + rs0;
        l1 = l1 * al1 + rs1;

#pragma unroll
        for (int nt = 0; nt < 8; nt++) {
            o[nt][0] *= al0; o[nt][1] *= al0;
            o[nt][2] *= al1; o[nt][3] *= al1;
        }

        // ---- P -> warp-private smem rows (tf32-rounded) ----
#pragma unroll
        for (int nt = 0; nt < 8; nt++) {
            float2 p0 = make_float2(rna_tf32(sv[nt][0]), rna_tf32(sv[nt][1]));
            *(float2*)(&Ps[qr0 * PSTR + nt * 8 + qd * 2]) = p0;
            float2 p1 = make_float2(rna_tf32(sv[nt][2]), rna_tf32(sv[nt][3]));
            *(float2*)(&Ps[qr1 * PSTR + nt * 8 + qd * 2]) = p1;
        }
        __syncwarp();

        // ---- O += P V ----
#pragma unroll
        for (int ks = 0; ks < 8; ks++) {
            uint32_t pa[4];
            const int pc = ks * 8 + qd;
            pa[0] = __float_as_uint(Ps[qr0 * PSTR + pc]);
            pa[1] = __float_as_uint(Ps[qr1 * PSTR + pc]);
            pa[2] = __float_as_uint(Ps[qr0 * PSTR + pc + 4]);
            pa[3] = __float_as_uint(Ps[qr1 * PSTR + pc + 4]);
            const float* v0 = &Vs[(ks * 8 + qd) * VSTR + grp];
            const float* v1 = &Vs[(ks * 8 + qd + 4) * VSTR + grp];
#pragma unroll
            for (int nt = 0; nt < 8; nt++)
                mma_tf32(o[nt], pa,
                         __float_as_uint(v0[nt * 8]), __float_as_uint(v1[nt * 8]));
        }
        __syncwarp();
    }

    // ---- epilogue: normalize + tf32-round, store g_att in A-perm layout ----
    const float i0 = 1.f / l0, i1 = 1.f / l1;
    const int mbq = qtile * 8 + warp;   // 16-row block index of rows qbase+warp*16
#pragma unroll
    for (int nt = 0; nt < 8; nt++) {
        const int kb = h * 8 + nt;
        float* blk = att + ((size_t)mbq * KBC + kb) * 128;
#pragma unroll
        for (int e = 0; e < 2; e++) {
            const int cb = 2 * qd + e;
            const int lane2 = grp * 4 + (cb & 3);
            const int jhi = ((cb >> 2) & 1) * 2;
            blk[lane2 * 4 + jhi]     = rna_tf32(o[nt][e]     * i0);
            blk[lane2 * 4 + jhi + 1] = rna_tf32(o[nt][2 + e] * i1);
        }
    }
}

// ---------------------------------------------------------------------------
// Launch
// ---------------------------------------------------------------------------
extern "C" void kernel_launch(void* const* d_in, const int* in_sizes, int n_in,
                              void* d_out, int out_size)
{
    const float* x      = (const float*)d_in[0];
    // d_in[1] = attention_mask: exact causal triu -> handled analytically
    const float* W_attn = (const float*)d_in[2];
    const float* b_attn = (const float*)d_in[3];
    const float* W_proj = (const float*)d_in[4];
    const float* b_proj = (const float*)d_in[5];
    float* out = (float*)d_out;

    float *qkv_p, *att_p, *xp_p, *wtp_p, *wpp_p, *ba_p;
    cudaGetSymbolAddress((void**)&qkv_p, g_qkv);
    cudaGetSymbolAddress((void**)&att_p, g_att);
    cudaGetSymbolAddress((void**)&xp_p,  g_xp);
    cudaGetSymbolAddress((void**)&wtp_p, g_wtp);
    cudaGetSymbolAddress((void**)&wpp_p, g_wpp);
    cudaGetSymbolAddress((void**)&ba_p,  g_ba);

    // 0) prep: permute + tf32-round operands; fold 0.125 into W_attn Q cols + b_attn
    {
        int nA = (S_LEN * C_DIM) / 4;
        permA_kernel<<<(nA + 255) / 256, 256>>>(x, xp_p, S_LEN, C_DIM);

        int nB1 = (3 * C_DIM * C_DIM) / 2;
        permB_kernel<<<(nB1 + 255) / 256, 256>>>(W_attn, wtp_p, C_DIM, 3 * C_DIM, C_DIM);

        int nB2 = (C_DIM * C_DIM) / 2;
        permB_kernel<<<(nB2 + 255) / 256, 256>>>(W_proj, wpp_p, C_DIM, C_DIM, 0);

        bias_prep_kernel<<<(3 * C_DIM + 255) / 256, 256>>>(b_attn, ba_p, 3 * C_DIM, C_DIM);
    }

    cudaFuncSetAttribute(gemm_mma_kernel<true>,
                         cudaFuncAttributeMaxDynamicSharedMemorySize, GSMEM_DYN);
    cudaFuncSetAttribute(gemm_mma_kernel<false>,
                         cudaFuncAttributeMaxDynamicSharedMemorySize, GSMEM_DYN);

    // 1) qkv = x @ W_attn + b_attn  (rounded output, Q pre-scaled)
    {
        dim3 grid((3 * C_DIM) / 128, S_LEN / 128);
        gemm_mma_kernel<true><<<grid, 256, GSMEM_DYN>>>(
            S_LEN, 3 * C_DIM, C_DIM, xp_p, wtp_p, ba_p, qkv_p);
    }

    // 2) causal flash attention (256 threads, 128-q-row tiles)
    {
        cudaFuncSetAttribute(attn_mma_kernel,
                             cudaFuncAttributeMaxDynamicSharedMemorySize, ASMEM_DYN);
        dim3 grid(S_LEN / 128, H_NUM);
        attn_mma_kernel<<<grid, 256, ASMEM_DYN>>>(qkv_p, att_p);
    }

    // 3) out = att @ W_proj + b_proj
    {
        dim3 grid(C_DIM / 128, S_LEN / 128);
        gemm_mma_kernel<false><<<grid, 256, GSMEM_DYN>>>(
            S_LEN, C_DIM, C_DIM, att_p, wpp_p, b_proj, out);
    }
}

// round 7
// speedup vs baseline: 4.0541x; 1.1322x over previous
#include <cuda_runtime.h>
#include <cuda_bf16.h>
#include <cstdint>
#include <math.h>

#define S_LEN 4096
#define C_DIM 1024
#define H_NUM 16
#define HD    64
#define KBC   (C_DIM / 8)

// Scratch (__device__ globals)
__device__ float g_qp [(size_t)H_NUM * 256 * 8 * 128];  // Q A-perm per head
__device__ float g_kp [(size_t)H_NUM * 512 * 8 * 64];   // K B-perm per head
__device__ float g_vp [(size_t)H_NUM * 512 * 8 * 64];   // V B-perm per head
__device__ float g_att[(size_t)S_LEN * C_DIM];          // attention out, A-perm
__device__ float g_xp [(size_t)S_LEN * C_DIM];          // x, A-perm
__device__ float g_wtp[(size_t)3 * C_DIM * C_DIM];      // W_attn B-perm (Q cols pre-scaled)
__device__ float g_wpp[(size_t)C_DIM * C_DIM];          // W_proj B-perm
__device__ float g_ba [3 * C_DIM];                      // b_attn, Q part pre-scaled

// ---------------------------------------------------------------------------
__device__ __forceinline__ float rna_tf32(float x) {
    uint32_t t;
    asm("cvt.rna.tf32.f32 %0, %1;" : "=r"(t) : "f"(x));
    return __uint_as_float(t);
}

__device__ __forceinline__ void cp16(void* s, const float* g) {
    uint32_t sa = (uint32_t)__cvta_generic_to_shared(s);
    asm volatile("cp.async.cg.shared.global [%0], [%1], 16;"
                 :: "r"(sa), "l"(__cvta_generic_to_global(g)));
}

// m16n8k8 tf32 mma. A row-major, B col-major.
__device__ __forceinline__ void mma_tf32(float c[4], const uint32_t a[4],
                                         uint32_t b0, uint32_t b1) {
    asm volatile(
        "mma.sync.aligned.m16n8k8.row.col.f32.tf32.tf32.f32 "
        "{%0,%1,%2,%3}, {%4,%5,%6,%7}, {%8,%9}, {%0,%1,%2,%3};"
        : "+f"(c[0]), "+f"(c[1]), "+f"(c[2]), "+f"(c[3])
        : "r"(a[0]), "r"(a[1]), "r"(a[2]), "r"(a[3]), "r"(b0), "r"(b1));
}

// ---------------------------------------------------------------------------
// Prep kernels (unchanged)
// ---------------------------------------------------------------------------
__global__ __launch_bounds__(256) void permA_kernel(
    const float* __restrict__ in, float* __restrict__ out, int M, int K)
{
    int cid = blockIdx.x * 256 + threadIdx.x;
    if (cid >= (M * K) / 4) return;
    const int per_mb = (K >> 3) * 32;
    int mb  = cid / per_mb;
    int rem = cid - mb * per_mb;
    int kb  = rem >> 5;
    int lane = rem & 31;
    int g = lane >> 2, q = lane & 3;
    size_t r = mb * 16 + g, c = kb * 8 + q;
    float4 o;
    o.x = rna_tf32(in[r * K + c]);
    o.y = rna_tf32(in[(r + 8) * K + c]);
    o.z = rna_tf32(in[r * K + c + 4]);
    o.w = rna_tf32(in[(r + 8) * K + c + 4]);
    ((float4*)out)[cid] = o;
}

__global__ __launch_bounds__(256) void permB_kernel(
    const float* __restrict__ W, float* __restrict__ out,
    int K, int N, int scaleN)
{
    int cid = blockIdx.x * 256 + threadIdx.x;
    if (cid >= (N * K) / 2) return;
    const int per_nb = (K >> 3) * 32;
    int nb  = cid / per_nb;
    int rem = cid - nb * per_nb;
    int kb  = rem >> 5;
    int lane = rem & 31;
    int g = lane >> 2, q = lane & 3;
    size_t n = nb * 8 + g, k = kb * 8 + q;
    float s = (n < (size_t)scaleN) ? 0.125f : 1.f;
    float2 o;
    o.x = rna_tf32(W[k * N + n] * s);
    o.y = rna_tf32(W[(k + 4) * N + n] * s);
    ((float2*)out)[cid] = o;
}

__global__ __launch_bounds__(256) void bias_prep_kernel(
    const float* __restrict__ b, float* __restrict__ o, int n, int scaleN)
{
    int i = blockIdx.x * 256 + threadIdx.x;
    if (i < n) o[i] = b[i] * (i < scaleN ? 0.125f : 1.f);
}

// ---------------------------------------------------------------------------
// tf32 mma.sync GEMM, CTA 128x128, 128 threads (4 warps, 2x2), warp tile 64x64.
// BK=32, 3-stage cp.async. MODE 0: plain bias epilogue to row-major C.
// MODE 1: qkv epilogue — bias + rna round + scatter into Qp/Kp/Vp packed.
// ---------------------------------------------------------------------------
#define GSTAGE_F 8192
#define GSMEM_DYN (3 * GSTAGE_F * 4)

extern __shared__ float gsm[];

template<int MODE>
__global__ __launch_bounds__(128, 2) void gemm_mma_kernel(
    int M, int N, int K,
    const float* __restrict__ Ap,
    const float* __restrict__ Bp,
    const float* __restrict__ bias,
    float* __restrict__ C,          // MODE 0 out
    float* __restrict__ Qp,         // MODE 1 outs
    float* __restrict__ Kp,
    float* __restrict__ Vp)
{
    const int tid  = threadIdx.x;
    const int wid  = tid >> 5;
    const int lane = tid & 31;
    const int g    = lane >> 2, q = lane & 3;
    const int bm   = blockIdx.y * 128;
    const int bn   = blockIdx.x * 128;
    const int mb0  = (wid >> 1) * 4;     // 4 m-blocks per warp
    const int nb0  = (wid & 1) * 8;      // 8 n-blocks per warp
    const int KB   = K >> 3;
    const int nch  = K >> 5;

    float acc[4][8][4];
#pragma unroll
    for (int i = 0; i < 4; i++)
#pragma unroll
        for (int j = 0; j < 8; j++)
#pragma unroll
            for (int e = 0; e < 4; e++) acc[i][j][e] = 0.f;

    auto load_stage = [&](int s, int ch) {
        float* As = gsm + s * GSTAGE_F;
        float* Bs = As + 4096;
        const int kb0 = ch * 4;
#pragma unroll
        for (int it = 0; it < 8; it++) {            // A: 1024 float4
            int idx = tid + it * 128;
            int mb = idx >> 7, rem = idx & 127;
            int kb = rem >> 5, l = rem & 31;
            const float* src = Ap +
                ((size_t)((bm >> 4) + mb) * KB + kb0 + kb) * 128 + l * 4;
            cp16(As + idx * 4, src);
        }
#pragma unroll
        for (int it = 0; it < 8; it++) {            // B: 1024 float4
            int idx = tid + it * 128;
            int nb = idx >> 6, rem = idx & 63;
            int kb = rem >> 4, l4 = rem & 15;
            const float* src = Bp +
                ((size_t)((bn >> 3) + nb) * KB + kb0 + kb) * 64 + l4 * 4;
            cp16(Bs + idx * 4, src);
        }
        asm volatile("cp.async.commit_group;" ::: "memory");
    };

    load_stage(0, 0);
    load_stage(1, 1);

    for (int ch = 0; ch < nch; ch++) {
        if (ch + 2 < nch)
            asm volatile("cp.async.wait_group 1;" ::: "memory");
        else
            asm volatile("cp.async.wait_group 0;" ::: "memory");
        __syncthreads();

        if (ch + 2 < nch) load_stage((ch + 2) % 3, ch + 2);

        const float* As = gsm + (ch % 3) * GSTAGE_F;
        const float* Bs = As + 4096;

#pragma unroll
        for (int ks = 0; ks < 4; ks++) {
            float4 afr[4];
            float2 bfr[8];
#pragma unroll
            for (int i = 0; i < 4; i++)
                afr[i] = *(const float4*)(As + (mb0 + i) * 512 + ks * 128 + lane * 4);
#pragma unroll
            for (int j = 0; j < 8; j++)
                bfr[j] = *(const float2*)(Bs + (nb0 + j) * 256 + ks * 64 + lane * 2);
#pragma unroll
            for (int i = 0; i < 4; i++)
#pragma unroll
                for (int j = 0; j < 8; j++)
                    mma_tf32(acc[i][j], (const uint32_t*)&afr[i],
                             __float_as_uint(bfr[j].x), __float_as_uint(bfr[j].y));
        }
    }

    if (MODE == 0) {
#pragma unroll
        for (int j = 0; j < 8; j++) {
            const int col = bn + (wid & 1) * 64 + j * 8 + 2 * q;
            const float2 bv = *(const float2*)(bias + col);
#pragma unroll
            for (int i = 0; i < 4; i++) {
                const int r0 = bm + (wid >> 1) * 64 + i * 16 + g;
                float2 o0, o1;
                o0.x = acc[i][j][0] + bv.x;
                o0.y = acc[i][j][1] + bv.y;
                o1.x = acc[i][j][2] + bv.x;
                o1.y = acc[i][j][3] + bv.y;
                *(float2*)(C + (size_t)r0 * N + col) = o0;
                *(float2*)(C + (size_t)(r0 + 8) * N + col) = o1;
            }
        }
    } else {
        // qkv scatter epilogue: section 0=Q, 1=K, 2=V
        const int sec = bn >> 10;
        const int hh  = ((bn & 1023) >> 6) + (wid & 1);
#pragma unroll
        for (int j = 0; j < 8; j++) {
            const int col = bn + (wid & 1) * 64 + j * 8 + 2 * q;
            const float2 bv = *(const float2*)(bias + col);
            const int dq0 = 2 * q;             // within 8-col block
#pragma unroll
            for (int i = 0; i < 4; i++) {
                float v00 = rna_tf32(acc[i][j][0] + bv.x);   // row g,   col dq0
                float v01 = rna_tf32(acc[i][j][1] + bv.y);   // row g,   col dq0+1
                float v10 = rna_tf32(acc[i][j][2] + bv.x);   // row g+8, col dq0
                float v11 = rna_tf32(acc[i][j][3] + bv.y);   // row g+8, col dq0+1
                if (sec == 0) {
                    const int mb = (bm >> 4) + (wid >> 1) * 4 + i;
                    float* base = Qp + ((size_t)(hh * 256 + mb) * 8 + j) * 128;
                    const int l0 = g * 4 + (dq0 & 3);
                    const int l1 = g * 4 + ((dq0 + 1) & 3);
                    const int el = 2 * (q >> 1);
                    base[l0 * 4 + el]     = v00;
                    base[l1 * 4 + el]     = v01;
                    base[l0 * 4 + el + 1] = v10;
                    base[l1 * 4 + el + 1] = v11;
                } else if (sec == 1) {
                    const int nb = (bm >> 3) + (wid >> 1) * 8 + i * 2;
                    float* base = Kp + ((size_t)(hh * 512 + nb) * 8 + j) * 64;
                    const int l0 = g * 4 + (dq0 & 3);
                    const int l1 = g * 4 + ((dq0 + 1) & 3);
                    const int el = q >> 1;
                    base[l0 * 2 + el]          = v00;
                    base[l1 * 2 + el]          = v01;
                    base[512 + l0 * 2 + el]    = v10;   // nb+1
                    base[512 + l1 * 2 + el]    = v11;
                } else {
                    const int kb = (bm >> 3) + (wid >> 1) * 8 + i * 2;
                    float* base = Vp + ((size_t)(hh * 512 + kb) * 8 + j) * 64;
                    const int l0 = dq0 * 4 + (g & 3);
                    const int l1 = (dq0 + 1) * 4 + (g & 3);
                    const int el = g >> 2;
                    base[l0 * 2 + el]          = v00;
                    base[l1 * 2 + el]          = v01;
                    base[512 + l0 * 2 + el]    = v10;   // kb+1
                    base[512 + l1 * 2 + el]    = v11;
                }
            }
        }
    }
}

// ---------------------------------------------------------------------------
// Causal flash attention, mma.sync tf32, packed operands.
// CTA = (head, 128-q-rows), 256 threads = 8 warps x 16-row strips.
// kv tiles of 64; K/V arrive fragment-packed (B-frag = 1 LDS.64).
// P staged in A-perm smem (A-frag = 1 LDS.128). Out -> g_att A-perm.
// ---------------------------------------------------------------------------
#define AKV_F 4096                               // floats per K (or V) tile
#define ASTAGE_F (2 * AKV_F)                     // K+V per stage
#define AP_F (8 * 1024)                          // P: 8 warps x 1024
#define ASMEM_DYN ((2 * ASTAGE_F + AP_F) * 4)    // 98304 B

extern __shared__ float asmem[];

__global__ __launch_bounds__(256) void attn_mma_kernel(
    const float* __restrict__ Qp, const float* __restrict__ Kp,
    const float* __restrict__ Vp, float* __restrict__ att)
{
    float* Pp = asmem + 2 * ASTAGE_F;

    const int tid   = threadIdx.x;
    const int warp  = tid >> 5;
    const int lane  = tid & 31;
    const int grp   = lane >> 2;
    const int qd    = lane & 3;
    const int h     = blockIdx.y;
    const int qtile = gridDim.x - 1 - blockIdx.x;
    const int qbase = qtile * 128;
    const int qr0   = warp * 16 + grp;
    const int njt   = 2 * qtile + 2;

    // ---- Q fragments: vector loads from packed Qp ----
    uint32_t qa[8][4];
    {
        const float* Qb = Qp + ((size_t)(h * 256 + qtile * 8 + warp) * 8) * 128;
#pragma unroll
        for (int ks = 0; ks < 8; ks++) {
            float4 v = *(const float4*)(Qb + ks * 128 + lane * 4);
            qa[ks][0] = __float_as_uint(v.x);
            qa[ks][1] = __float_as_uint(v.y);
            qa[ks][2] = __float_as_uint(v.z);
            qa[ks][3] = __float_as_uint(v.w);
        }
    }

    auto load_kv = [&](int s, int jt) {
        float* Ks = asmem + s * ASTAGE_F;
        float* Vs = Ks + AKV_F;
        const float* Kg = Kp + (size_t)(h * 512 + jt * 8) * 512;
        const float* Vg = Vp + (size_t)(h * 512 + jt * 8) * 512;
#pragma unroll
        for (int it = 0; it < 4; it++) {
            int idx = tid + it * 256;
            cp16(Ks + idx * 4, Kg + idx * 4);
            cp16(Vs + idx * 4, Vg + idx * 4);
        }
        asm volatile("cp.async.commit_group;" ::: "memory");
    };

    load_kv(0, 0);

    float o[8][4];
#pragma unroll
    for (int nt = 0; nt < 8; nt++)
#pragma unroll
        for (int e = 0; e < 4; e++) o[nt][e] = 0.f;
    float m0 = -INFINITY, m1 = -INFINITY, l0 = 0.f, l1 = 0.f;

    for (int jt = 0; jt < njt; jt++) {
        const int s = jt & 1;
        if (jt) __syncthreads();
        if (jt + 1 < njt) load_kv(s ^ 1, jt + 1);
        if (jt + 1 < njt)
            asm volatile("cp.async.wait_group 1;" ::: "memory");
        else
            asm volatile("cp.async.wait_group 0;" ::: "memory");
        __syncthreads();

        if (warp < 4 && jt == njt - 1) continue;   // fully future-masked

        const float* Ks = asmem + s * ASTAGE_F;
        const float* Vs = Ks + AKV_F;
        const int kvbase = jt * 64;

        // ---- S = Q K^T : B-frag = single LDS.64 ----
        float sv[8][4];
#pragma unroll
        for (int nt = 0; nt < 8; nt++)
#pragma unroll
            for (int e = 0; e < 4; e++) sv[nt][e] = 0.f;

#pragma unroll
        for (int ks = 0; ks < 8; ks++) {
#pragma unroll
            for (int nt = 0; nt < 8; nt++) {
                float2 b = *(const float2*)(Ks + (nt * 8 + ks) * 64 + lane * 2);
                mma_tf32(sv[nt], qa[ks],
                         __float_as_uint(b.x), __float_as_uint(b.y));
            }
        }

        // ---- causal mask ----
        if (jt >= 2 * qtile) {
            const int rg0 = qbase + qr0, rg1 = rg0 + 8;
#pragma unroll
            for (int nt = 0; nt < 8; nt++) {
                int cg = kvbase + nt * 8 + qd * 2;
                if (cg     > rg0) sv[nt][0] = -INFINITY;
                if (cg + 1 > rg0) sv[nt][1] = -INFINITY;
                if (cg     > rg1) sv[nt][2] = -INFINITY;
                if (cg + 1 > rg1) sv[nt][3] = -INFINITY;
            }
        }

        // ---- online softmax ----
        float mt0 = -INFINITY, mt1 = -INFINITY;
#pragma unroll
        for (int nt = 0; nt < 8; nt++) {
            mt0 = fmaxf(mt0, fmaxf(sv[nt][0], sv[nt][1]));
            mt1 = fmaxf(mt1, fmaxf(sv[nt][2], sv[nt][3]));
        }
        mt0 = fmaxf(mt0, __shfl_xor_sync(0xffffffffu, mt0, 1));
        mt0 = fmaxf(mt0, __shfl_xor_sync(0xffffffffu, mt0, 2));
        mt1 = fmaxf(mt1, __shfl_xor_sync(0xffffffffu, mt1, 1));
        mt1 = fmaxf(mt1, __shfl_xor_sync(0xffffffffu, mt1, 2));

        const float mn0 = fmaxf(m0, mt0), mn1 = fmaxf(m1, mt1);
        const float al0 = __expf(m0 - mn0), al1 = __expf(m1 - mn1);
        m0 = mn0; m1 = mn1;

        float rs0 = 0.f, rs1 = 0.f;
#pragma unroll
        for (int nt = 0; nt < 8; nt++) {
            sv[nt][0] = __expf(sv[nt][0] - mn0);
            sv[nt][1] = __expf(sv[nt][1] - mn0);
            sv[nt][2] = __expf(sv[nt][2] - mn1);
            sv[nt][3] = __expf(sv[nt][3] - mn1);
            rs0 += sv[nt][0] + sv[nt][1];
            rs1 += sv[nt][2] + sv[nt][3];
        }
        rs0 += __shfl_xor_sync(0xffffffffu, rs0, 1);
        rs0 += __shfl_xor_sync(0xffffffffu, rs0, 2);
        rs1 += __shfl_xor_sync(0xffffffffu, rs1, 1);
        rs1 += __shfl_xor_sync(0xffffffffu, rs1, 2);
        l0 = l0 * al0 + rs0;
        l1 = l1 * al1 + rs1;

#pragma unroll
        for (int nt = 0; nt < 8; nt++) {
            o[nt][0] *= al0; o[nt][1] *= al0;
            o[nt][2] *= al1; o[nt][3] *= al1;
        }

        // ---- P -> warp-private A-perm smem ----
        {
            float* Pw = Pp + warp * 1024;
            const int l0i = grp * 4 + ((2 * qd) & 3);
            const int l1i = grp * 4 + ((2 * qd + 1) & 3);
            const int el  = 2 * (qd >> 1);
#pragma unroll
            for (int nt = 0; nt < 8; nt++) {
                float* c = Pw + nt * 128;
                c[l0i * 4 + el]     = rna_tf32(sv[nt][0]);
                c[l1i * 4 + el]     = rna_tf32(sv[nt][1]);
                c[l0i * 4 + el + 1] = rna_tf32(sv[nt][2]);
                c[l1i * 4 + el + 1] = rna_tf32(sv[nt][3]);
            }
        }
        __syncwarp();

        // ---- O += P V : A-frag = 1 LDS.128, B-frag = 1 LDS.64 ----
#pragma unroll
        for (int ks = 0; ks < 8; ks++) {
            float4 pav = *(const float4*)(Pp + warp * 1024 + ks * 128 + lane * 4);
            uint32_t pa[4] = { __float_as_uint(pav.x), __float_as_uint(pav.y),
                               __float_as_uint(pav.z), __float_as_uint(pav.w) };
#pragma unroll
            for (int nt = 0; nt < 8; nt++) {
                float2 b = *(const float2*)(Vs + (ks * 8 + nt) * 64 + lane * 2);
                mma_tf32(o[nt], pa,
                         __float_as_uint(b.x), __float_as_uint(b.y));
            }
        }
        __syncwarp();
    }

    // ---- epilogue: normalize + round, store g_att in A-perm ----
    const float i0 = 1.f / l0, i1 = 1.f / l1;
    const int mbq = qtile * 8 + warp;
#pragma unroll
    for (int nt = 0; nt < 8; nt++) {
        const int kb = h * 8 + nt;
        float* blk = att + ((size_t)mbq * KBC + kb) * 128;
#pragma unroll
        for (int e = 0; e < 2; e++) {
            const int cb = 2 * qd + e;
            const int lane2 = grp * 4 + (cb & 3);
            const int jhi = ((cb >> 2) & 1) * 2;
            blk[lane2 * 4 + jhi]     = rna_tf32(o[nt][e]     * i0);
            blk[lane2 * 4 + jhi + 1] = rna_tf32(o[nt][2 + e] * i1);
        }
    }
}

// ---------------------------------------------------------------------------
// Launch
// ---------------------------------------------------------------------------
extern "C" void kernel_launch(void* const* d_in, const int* in_sizes, int n_in,
                              void* d_out, int out_size)
{
    const float* x      = (const float*)d_in[0];
    // d_in[1] = attention_mask: exact causal triu -> handled analytically
    const float* W_attn = (const float*)d_in[2];
    const float* b_attn = (const float*)d_in[3];
    const float* W_proj = (const float*)d_in[4];
    const float* b_proj = (const float*)d_in[5];
    float* out = (float*)d_out;

    float *qp_p, *kp_p, *vp_p, *att_p, *xp_p, *wtp_p, *wpp_p, *ba_p;
    cudaGetSymbolAddress((void**)&qp_p,  g_qp);
    cudaGetSymbolAddress((void**)&kp_p,  g_kp);
    cudaGetSymbolAddress((void**)&vp_p,  g_vp);
    cudaGetSymbolAddress((void**)&att_p, g_att);
    cudaGetSymbolAddress((void**)&xp_p,  g_xp);
    cudaGetSymbolAddress((void**)&wtp_p, g_wtp);
    cudaGetSymbolAddress((void**)&wpp_p, g_wpp);
    cudaGetSymbolAddress((void**)&ba_p,  g_ba);

    // 0) prep
    {
        int nA = (S_LEN * C_DIM) / 4;
        permA_kernel<<<(nA + 255) / 256, 256>>>(x, xp_p, S_LEN, C_DIM);

        int nB1 = (3 * C_DIM * C_DIM) / 2;
        permB_kernel<<<(nB1 + 255) / 256, 256>>>(W_attn, wtp_p, C_DIM, 3 * C_DIM, C_DIM);

        int nB2 = (C_DIM * C_DIM) / 2;
        permB_kernel<<<(nB2 + 255) / 256, 256>>>(W_proj, wpp_p, C_DIM, C_DIM, 0);

        bias_prep_kernel<<<(3 * C_DIM + 255) / 256, 256>>>(b_attn, ba_p, 3 * C_DIM, C_DIM);
    }

    cudaFuncSetAttribute(gemm_mma_kernel<0>,
                         cudaFuncAttributeMaxDynamicSharedMemorySize, GSMEM_DYN);
    cudaFuncSetAttribute(gemm_mma_kernel<1>,
                         cudaFuncAttributeMaxDynamicSharedMemorySize, GSMEM_DYN);

    // 1) qkv GEMM -> packed Qp/Kp/Vp
    {
        dim3 grid((3 * C_DIM) / 128, S_LEN / 128);
        gemm_mma_kernel<1><<<grid, 128, GSMEM_DYN>>>(
            S_LEN, 3 * C_DIM, C_DIM, xp_p, wtp_p, ba_p,
            nullptr, qp_p, kp_p, vp_p);
    }

    // 2) causal flash attention
    {
        cudaFuncSetAttribute(attn_mma_kernel,
                             cudaFuncAttributeMaxDynamicSharedMemorySize, ASMEM_DYN);
        dim3 grid(S_LEN / 128, H_NUM);
        attn_mma_kernel<<<grid, 256, ASMEM_DYN>>>(qp_p, kp_p, vp_p, att_p);
    }

    // 3) proj GEMM
    {
        dim3 grid(C_DIM / 128, S_LEN / 128);
        gemm_mma_kernel<0><<<grid, 128, GSMEM_DYN>>>(
            S_LEN, C_DIM, C_DIM, att_p, wpp_p, b_proj,
            out, nullptr, nullptr, nullptr);
    }
}

// round 9
// speedup vs baseline: 7.4987x; 1.8496x over previous
#include <cuda_runtime.h>
#include <cuda_fp16.h>
#include <cstdint>
#include <math.h>

#define S_LEN 4096
#define C_DIM 1024
#define H_NUM 16
#define HD    64
#define KB16  (C_DIM / 16)    // 64 k-blocks of 16

// Scratch (__device__ globals). All mma-fragment-packed, fp16.
__device__ uint32_t g_qp [(size_t)H_NUM * 256 * 4 * 32 * 4];   // Q A-perm16 per head
__device__ uint32_t g_kp [(size_t)H_NUM * 512 * 4 * 32 * 2];   // K B-perm16 per head
__device__ __half   g_vp [(size_t)H_NUM * 256 * 8 * 32 * 4];   // V B-perm16 (kv-major)
__device__ uint32_t g_att[(size_t)256 * 64 * 32 * 4];          // attn out, A-perm16
__device__ uint32_t g_xp [(size_t)256 * 64 * 32 * 4];          // x, A-perm16
__device__ uint32_t g_wtp[(size_t)384 * 64 * 32 * 2];          // W_attn B-perm16 (Q pre-scaled)
__device__ uint32_t g_wpp[(size_t)128 * 64 * 32 * 2];          // W_proj B-perm16
__device__ float    g_ba [3 * C_DIM];                          // b_attn, Q part pre-scaled

// ---------------------------------------------------------------------------
__device__ __forceinline__ void cp16(void* s, const void* g) {
    uint32_t sa = (uint32_t)__cvta_generic_to_shared(s);
    asm volatile("cp.async.cg.shared.global [%0], [%1], 16;"
                 :: "r"(sa), "l"(__cvta_generic_to_global(g)));
}

__device__ __forceinline__ uint32_t h2u(__half2 h) {
    return *reinterpret_cast<uint32_t*>(&h);
}

// m16n8k16 fp16 mma, fp32 accum. A row-major, B col-major.
// A frag (4 regs): a0=(g,2q:2q+1) a1=(g+8,2q:2q+1) a2=(g,2q+8:2q+9) a3=(g+8,2q+8:2q+9)
// B frag (2 regs): b0=(k=2q:2q+1, n=g) b1=(k=2q+8:2q+9, n=g)
// C frag: c0=(g,2q) c1=(g,2q+1) c2=(g+8,2q) c3=(g+8,2q+1)
__device__ __forceinline__ void mma_f16(float c[4], const uint32_t a[4],
                                        uint32_t b0, uint32_t b1) {
    asm volatile(
        "mma.sync.aligned.m16n8k16.row.col.f32.f16.f16.f32 "
        "{%0,%1,%2,%3}, {%4,%5,%6,%7}, {%8,%9}, {%0,%1,%2,%3};"
        : "+f"(c[0]), "+f"(c[1]), "+f"(c[2]), "+f"(c[3])
        : "r"(a[0]), "r"(a[1]), "r"(a[2]), "r"(a[3]), "r"(b0), "r"(b1));
}

// ---------------------------------------------------------------------------
// Prep: A-perm16 of x [M,K]f32 -> [mb][kb16][lane][4xb32(h2)]
// ---------------------------------------------------------------------------
__global__ __launch_bounds__(256) void permA16_kernel(
    const float* __restrict__ in, uint32_t* __restrict__ out, int M, int K)
{
    int cid = blockIdx.x * 256 + threadIdx.x;
    if (cid >= (M / 16) * (K / 16) * 32) return;
    const int per_mb = (K >> 4) * 32;
    int mb  = cid / per_mb;
    int rem = cid - mb * per_mb;
    int kb  = rem >> 5;
    int lane = rem & 31;
    int g = lane >> 2, q = lane & 3;
    size_t r = mb * 16 + g, c = kb * 16 + 2 * q;
    uint4 o;
    o.x = h2u(__floats2half2_rn(in[r * K + c],           in[r * K + c + 1]));
    o.y = h2u(__floats2half2_rn(in[(r + 8) * K + c],     in[(r + 8) * K + c + 1]));
    o.z = h2u(__floats2half2_rn(in[r * K + c + 8],       in[r * K + c + 9]));
    o.w = h2u(__floats2half2_rn(in[(r + 8) * K + c + 8], in[(r + 8) * K + c + 9]));
    ((uint4*)out)[cid] = o;
}

// ---------------------------------------------------------------------------
// Prep: B-perm16 of W [K][N] -> [nb][kb16][lane][2xb32]; cols n<scaleN *0.125
// ---------------------------------------------------------------------------
__global__ __launch_bounds__(256) void permB16_kernel(
    const float* __restrict__ W, uint32_t* __restrict__ out,
    int K, int N, int scaleN)
{
    int cid = blockIdx.x * 256 + threadIdx.x;
    if (cid >= (N / 8) * (K / 16) * 32) return;
    const int per_nb = (K >> 4) * 32;
    int nb  = cid / per_nb;
    int rem = cid - nb * per_nb;
    int kb  = rem >> 5;
    int lane = rem & 31;
    int g = lane >> 2, q = lane & 3;
    size_t n = nb * 8 + g, k = kb * 16 + 2 * q;
    float s = (n < (size_t)scaleN) ? 0.125f : 1.f;
    uint2 o;
    o.x = h2u(__floats2half2_rn(W[k * N + n] * s,       W[(k + 1) * N + n] * s));
    o.y = h2u(__floats2half2_rn(W[(k + 8) * N + n] * s, W[(k + 9) * N + n] * s));
    ((uint2*)out)[cid] = o;
}

__global__ __launch_bounds__(256) void bias_prep_kernel(
    const float* __restrict__ b, float* __restrict__ o, int n, int scaleN)
{
    int i = blockIdx.x * 256 + threadIdx.x;
    if (i < n) o[i] = b[i] * (i < scaleN ? 0.125f : 1.f);
}

// ---------------------------------------------------------------------------
// fp16 mma.sync GEMM, CTA 128x128, 128 threads (4 warps 2x2), warp 64x64.
// BK=32 (2 kb16), 3-stage cp.async.
// MODE 0: fp32 bias epilogue -> row-major C.  MODE 1: qkv scatter -> Qp/Kp/Vp.
// ---------------------------------------------------------------------------
#define GSTAGE_U 4096                    // u32 per stage (A 2048 + B 2048)
#define GSMEM_DYN (3 * GSTAGE_U * 4)     // 49152 B

extern __shared__ uint32_t gsm[];

template<int MODE>
__global__ __launch_bounds__(128, 2) void gemm_f16_kernel(
    int M, int N, int K,
    const uint32_t* __restrict__ Ap,
    const uint32_t* __restrict__ Bp,
    const float* __restrict__ bias,
    float* __restrict__ C,
    uint32_t* __restrict__ Qp,
    uint32_t* __restrict__ Kp,
    __half* __restrict__ Vp)
{
    const int tid  = threadIdx.x;
    const int wid  = tid >> 5;
    const int lane = tid & 31;
    const int g    = lane >> 2, q = lane & 3;
    const int bm   = blockIdx.y * 128;
    const int bn   = blockIdx.x * 128;
    const int mb0  = (wid >> 1) * 4;
    const int nb0  = (wid & 1) * 8;
    const int KB   = K >> 4;
    const int nch  = K >> 5;

    float acc[4][8][4];
#pragma unroll
    for (int i = 0; i < 4; i++)
#pragma unroll
        for (int j = 0; j < 8; j++)
#pragma unroll
            for (int e = 0; e < 4; e++) acc[i][j][e] = 0.f;

    auto load_stage = [&](int s, int ch) {
        uint32_t* As = gsm + s * GSTAGE_U;
        uint32_t* Bs = As + 2048;
        const int kb0 = ch * 2;
#pragma unroll
        for (int it = 0; it < 4; it++) {          // A: 512 x 16B
            int idx = tid + it * 128;
            int mb = idx >> 6, rem = idx & 63;
            int kb = rem >> 5, l = rem & 31;
            const uint32_t* src = Ap +
                ((size_t)((bm >> 4) + mb) * KB + kb0 + kb) * 128 + l * 4;
            cp16(As + idx * 4, src);
        }
#pragma unroll
        for (int it = 0; it < 4; it++) {          // B: 512 x 16B
            int idx = tid + it * 128;
            int nb = idx >> 5, rem = idx & 31;
            int kb = rem >> 4, ll = rem & 15;
            const uint32_t* src = Bp +
                ((size_t)((bn >> 3) + nb) * KB + kb0 + kb) * 64 + ll * 4;
            cp16(Bs + idx * 4, src);
        }
        asm volatile("cp.async.commit_group;" ::: "memory");
    };

    load_stage(0, 0);
    load_stage(1, 1);

    for (int ch = 0; ch < nch; ch++) {
        if (ch + 2 < nch)
            asm volatile("cp.async.wait_group 1;" ::: "memory");
        else
            asm volatile("cp.async.wait_group 0;" ::: "memory");
        __syncthreads();

        if (ch + 2 < nch) load_stage((ch + 2) % 3, ch + 2);

        const uint32_t* As = gsm + (ch % 3) * GSTAGE_U;
        const uint32_t* Bs = As + 2048;

#pragma unroll
        for (int kb = 0; kb < 2; kb++) {
            uint4 afr[4];
            uint2 bfr[8];
#pragma unroll
            for (int i = 0; i < 4; i++)
                afr[i] = *(const uint4*)(As + ((mb0 + i) * 2 + kb) * 128 + lane * 4);
#pragma unroll
            for (int j = 0; j < 8; j++)
                bfr[j] = *(const uint2*)(Bs + ((nb0 + j) * 2 + kb) * 64 + lane * 2);
#pragma unroll
            for (int i = 0; i < 4; i++)
#pragma unroll
                for (int j = 0; j < 8; j++)
                    mma_f16(acc[i][j], (const uint32_t*)&afr[i], bfr[j].x, bfr[j].y);
        }
    }

    if (MODE == 0) {
#pragma unroll
        for (int j = 0; j < 8; j++) {
            const int col = bn + (wid & 1) * 64 + j * 8 + 2 * q;
            const float2 bv = *(const float2*)(bias + col);
#pragma unroll
            for (int i = 0; i < 4; i++) {
                const int r0 = bm + (wid >> 1) * 64 + i * 16 + g;
                float2 o0, o1;
                o0.x = acc[i][j][0] + bv.x;
                o0.y = acc[i][j][1] + bv.y;
                o1.x = acc[i][j][2] + bv.x;
                o1.y = acc[i][j][3] + bv.y;
                *(float2*)(C + (size_t)r0 * N + col) = o0;
                *(float2*)(C + (size_t)(r0 + 8) * N + col) = o1;
            }
        }
    } else {
        // qkv scatter: section 0=Q, 1=K, 2=V; hh = head
        const int sec = bn >> 10;
        const int hh  = ((bn & 1023) >> 6) + (wid & 1);
#pragma unroll
        for (int j = 0; j < 8; j++) {
            const int col = bn + (wid & 1) * 64 + j * 8 + 2 * q;
            const float2 bv = *(const float2*)(bias + col);
#pragma unroll
            for (int i = 0; i < 4; i++) {
                float v00 = acc[i][j][0] + bv.x;    // (row g,   d 2q)
                float v01 = acc[i][j][1] + bv.y;    // (row g,   d 2q+1)
                float v10 = acc[i][j][2] + bv.x;    // (row g+8, d 2q)
                float v11 = acc[i][j][3] + bv.y;    // (row g+8, d 2q+1)
                uint32_t p0 = h2u(__floats2half2_rn(v00, v01));
                uint32_t p1 = h2u(__floats2half2_rn(v10, v11));
                if (sec == 0) {
                    const int mb = (bm >> 4) + (wid >> 1) * 4 + i;
                    const int kb = j >> 1;
                    uint32_t* base = Qp +
                        (((size_t)(hh * 256 + mb) * 4 + kb) * 32 + lane) * 4 + (j & 1) * 2;
                    base[0] = p0;
                    base[1] = p1;
                } else if (sec == 1) {
                    const int nb = (bm >> 3) + (wid >> 1) * 8 + i * 2;
                    const int kb = j >> 1;
                    uint32_t* base = Kp +
                        (((size_t)(hh * 512 + nb) * 4 + kb) * 32 + lane) * 2 + (j & 1);
                    base[0]   = p0;          // kv row g     (nb)
                    base[256] = p1;          // kv row g+8   (nb+1): 4*32*2 = 256
                } else {
                    // V: PV B-frag pairs run along kv. For head-dim cols d=2q and
                    // d=2q+1 the target LANES differ by 4 (g' = 2q vs 2q+1):
                    //   lane(d)   = (2q)*4   + (g>>1)
                    //   lane(d+1) = (2q+1)*4 + (g>>1)   -> +4 lanes = +16 halves
                    const int kvb = (bm >> 4) + (wid >> 1) * 4 + i;
                    const int hi  = g & 1;
                    __half* b0 = Vp +
                        ((((size_t)(hh * 256 + kvb) * 8 + j) * 32 + 2 * q * 4 + (g >> 1)) * 4);
                    __half* b1 = b0 + 16;    // FIX: was +4 (wrong lane)
                    b0[hi]     = __float2half_rn(v00);   // half 0/1: kv rows 2q',2q'+1
                    b0[2 + hi] = __float2half_rn(v10);   // half 2/3: kv rows +8
                    b1[hi]     = __float2half_rn(v01);
                    b1[2 + hi] = __float2half_rn(v11);
                }
            }
        }
    }
}

// ---------------------------------------------------------------------------
// Causal flash attention, fp16 m16n8k16, P kept in registers (C->A reuse).
// CTA = (head, 128 q-rows), 256 threads = 8 warps x 16-row strips.
// kv tiles of 64, double-buffered cp.async (16KB/stage).
// ---------------------------------------------------------------------------
#define ASTAGE_U 4096                        // u32: K 2048 + V 2048
#define ASMEM_DYN (2 * ASTAGE_U * 4)         // 32768 B

extern __shared__ uint32_t asmem[];

__global__ __launch_bounds__(256) void attn_f16_kernel(
    const uint32_t* __restrict__ Qp, const uint32_t* __restrict__ Kp,
    const uint32_t* __restrict__ Vp, uint32_t* __restrict__ att)
{
    const int tid   = threadIdx.x;
    const int warp  = tid >> 5;
    const int lane  = tid & 31;
    const int grp   = lane >> 2;
    const int qd    = lane & 3;
    const int h     = blockIdx.y;
    const int qtile = gridDim.x - 1 - blockIdx.x;
    const int qbase = qtile * 128;
    const int qr0   = warp * 16 + grp;
    const int njt   = 2 * qtile + 2;

    // ---- Q fragments: 4 x LDG.128 from packed Qp ----
    uint32_t qa[4][4];
    {
        const uint4* Qb = (const uint4*)(Qp +
            ((size_t)(h * 256 + qtile * 8 + warp) * 4) * 128);
#pragma unroll
        for (int ks = 0; ks < 4; ks++) {
            uint4 v = Qb[ks * 32 + lane];
            qa[ks][0] = v.x; qa[ks][1] = v.y; qa[ks][2] = v.z; qa[ks][3] = v.w;
        }
    }

    auto load_kv = [&](int s, int jt) {
        uint32_t* Ks = asmem + s * ASTAGE_U;
        uint32_t* Vs = Ks + 2048;
        const uint32_t* Kg = Kp + (size_t)(h * 512 + jt * 8) * 256;
        const uint32_t* Vg = Vp + (size_t)(h * 256 + jt * 4) * 512;
#pragma unroll
        for (int it = 0; it < 2; it++) {
            int idx = tid + it * 256;
            cp16(Ks + idx * 4, Kg + idx * 4);
            cp16(Vs + idx * 4, Vg + idx * 4);
        }
        asm volatile("cp.async.commit_group;" ::: "memory");
    };

    load_kv(0, 0);

    float o[8][4];
#pragma unroll
    for (int nt = 0; nt < 8; nt++)
#pragma unroll
        for (int e = 0; e < 4; e++) o[nt][e] = 0.f;
    float m0 = -INFINITY, m1 = -INFINITY, l0 = 0.f, l1 = 0.f;

    for (int jt = 0; jt < njt; jt++) {
        const int s = jt & 1;
        if (jt) __syncthreads();
        if (jt + 1 < njt) load_kv(s ^ 1, jt + 1);
        if (jt + 1 < njt)
            asm volatile("cp.async.wait_group 1;" ::: "memory");
        else
            asm volatile("cp.async.wait_group 0;" ::: "memory");
        __syncthreads();

        if (warp < 4 && jt == njt - 1) continue;    // fully future-masked

        const uint32_t* Ks = asmem + s * ASTAGE_U;
        const uint32_t* Vs = Ks + 2048;
        const int kvbase = jt * 64;

        // ---- S = Q K^T ----
        float sv[8][4];
#pragma unroll
        for (int nt = 0; nt < 8; nt++)
#pragma unroll
            for (int e = 0; e < 4; e++) sv[nt][e] = 0.f;

#pragma unroll
        for (int ks = 0; ks < 4; ks++) {
#pragma unroll
            for (int nt = 0; nt < 8; nt++) {
                uint2 b = *(const uint2*)(Ks + ((nt * 4 + ks) * 32 + lane) * 2);
                mma_f16(sv[nt], qa[ks], b.x, b.y);
            }
        }

        // ---- causal mask ----
        if (jt >= 2 * qtile) {
            const int rg0 = qbase + qr0, rg1 = rg0 + 8;
#pragma unroll
            for (int nt = 0; nt < 8; nt++) {
                int cg = kvbase + nt * 8 + qd * 2;
                if (cg     > rg0) sv[nt][0] = -INFINITY;
                if (cg + 1 > rg0) sv[nt][1] = -INFINITY;
                if (cg     > rg1) sv[nt][2] = -INFINITY;
                if (cg + 1 > rg1) sv[nt][3] = -INFINITY;
            }
        }

        // ---- online softmax ----
        float mt0 = -INFINITY, mt1 = -INFINITY;
#pragma unroll
        for (int nt = 0; nt < 8; nt++) {
            mt0 = fmaxf(mt0, fmaxf(sv[nt][0], sv[nt][1]));
            mt1 = fmaxf(mt1, fmaxf(sv[nt][2], sv[nt][3]));
        }
        mt0 = fmaxf(mt0, __shfl_xor_sync(0xffffffffu, mt0, 1));
        mt0 = fmaxf(mt0, __shfl_xor_sync(0xffffffffu, mt0, 2));
        mt1 = fmaxf(mt1, __shfl_xor_sync(0xffffffffu, mt1, 1));
        mt1 = fmaxf(mt1, __shfl_xor_sync(0xffffffffu, mt1, 2));

        const float mn0 = fmaxf(m0, mt0), mn1 = fmaxf(m1, mt1);
        const float al0 = __expf(m0 - mn0), al1 = __expf(m1 - mn1);
        m0 = mn0; m1 = mn1;

        float rs0 = 0.f, rs1 = 0.f;
#pragma unroll
        for (int nt = 0; nt < 8; nt++) {
            sv[nt][0] = __expf(sv[nt][0] - mn0);
            sv[nt][1] = __expf(sv[nt][1] - mn0);
            sv[nt][2] = __expf(sv[nt][2] - mn1);
            sv[nt][3] = __expf(sv[nt][3] - mn1);
            rs0 += sv[nt][0] + sv[nt][1];
            rs1 += sv[nt][2] + sv[nt][3];
        }
        rs0 += __shfl_xor_sync(0xffffffffu, rs0, 1);
        rs0 += __shfl_xor_sync(0xffffffffu, rs0, 2);
        rs1 += __shfl_xor_sync(0xffffffffu, rs1, 1);
        rs1 += __shfl_xor_sync(0xffffffffu, rs1, 2);
        l0 = l0 * al0 + rs0;
        l1 = l1 * al1 + rs1;

#pragma unroll
        for (int nt = 0; nt < 8; nt++) {
            o[nt][0] *= al0; o[nt][1] *= al0;
            o[nt][2] *= al1; o[nt][3] *= al1;
        }

        // ---- P: pack C-frags directly into PV A-frags (no smem!) ----
        uint32_t p0[8], p1[8];
#pragma unroll
        for (int nt = 0; nt < 8; nt++) {
            p0[nt] = h2u(__floats2half2_rn(sv[nt][0], sv[nt][1]));
            p1[nt] = h2u(__floats2half2_rn(sv[nt][2], sv[nt][3]));
        }

        // ---- O += P V ----
#pragma unroll
        for (int ks = 0; ks < 4; ks++) {
            uint32_t pa[4] = { p0[2 * ks], p1[2 * ks], p0[2 * ks + 1], p1[2 * ks + 1] };
#pragma unroll
            for (int nt = 0; nt < 8; nt++) {
                uint2 b = *(const uint2*)(Vs + ((ks * 8 + nt) * 32 + lane) * 2);
                mma_f16(o[nt], pa, b.x, b.y);
            }
        }
    }

    // ---- epilogue: normalize + fp16 round, store g_att in A-perm16 ----
    const float i0 = 1.f / l0, i1 = 1.f / l1;
    const int mb = qtile * 8 + warp;
#pragma unroll
    for (int nt = 0; nt < 8; nt++) {
        const int kb = h * 4 + (nt >> 1);
        uint32_t* base = att +
            (((size_t)mb * 64 + kb) * 32 + lane) * 4 + (nt & 1) * 2;
        base[0] = h2u(__floats2half2_rn(o[nt][0] * i0, o[nt][1] * i0));
        base[1] = h2u(__floats2half2_rn(o[nt][2] * i1, o[nt][3] * i1));
    }
}

// ---------------------------------------------------------------------------
// Launch
// ---------------------------------------------------------------------------
extern "C" void kernel_launch(void* const* d_in, const int* in_sizes, int n_in,
                              void* d_out, int out_size)
{
    const float* x      = (const float*)d_in[0];
    // d_in[1] = attention_mask: exact causal triu -> handled analytically
    const float* W_attn = (const float*)d_in[2];
    const float* b_attn = (const float*)d_in[3];
    const float* W_proj = (const float*)d_in[4];
    const float* b_proj = (const float*)d_in[5];
    float* out = (float*)d_out;

    uint32_t *qp_p, *kp_p, *att_p, *xp_p, *wtp_p, *wpp_p;
    __half* vp_p;
    float* ba_p;
    cudaGetSymbolAddress((void**)&qp_p,  g_qp);
    cudaGetSymbolAddress((void**)&kp_p,  g_kp);
    cudaGetSymbolAddress((void**)&vp_p,  g_vp);
    cudaGetSymbolAddress((void**)&att_p, g_att);
    cudaGetSymbolAddress((void**)&xp_p,  g_xp);
    cudaGetSymbolAddress((void**)&wtp_p, g_wtp);
    cudaGetSymbolAddress((void**)&wpp_p, g_wpp);
    cudaGetSymbolAddress((void**)&ba_p,  g_ba);

    // 0) prep: fp16 permuted operands
    {
        int nA = 256 * 64 * 32;
        permA16_kernel<<<(nA + 255) / 256, 256>>>(x, xp_p, S_LEN, C_DIM);

        int nB1 = 384 * 64 * 32;
        permB16_kernel<<<(nB1 + 255) / 256, 256>>>(W_attn, wtp_p, C_DIM, 3 * C_DIM, C_DIM);

        int nB2 = 128 * 64 * 32;
        permB16_kernel<<<(nB2 + 255) / 256, 256>>>(W_proj, wpp_p, C_DIM, C_DIM, 0);

        bias_prep_kernel<<<(3 * C_DIM + 255) / 256, 256>>>(b_attn, ba_p, 3 * C_DIM, C_DIM);
    }

    cudaFuncSetAttribute(gemm_f16_kernel<0>,
                         cudaFuncAttributeMaxDynamicSharedMemorySize, GSMEM_DYN);
    cudaFuncSetAttribute(gemm_f16_kernel<1>,
                         cudaFuncAttributeMaxDynamicSharedMemorySize, GSMEM_DYN);

    // 1) qkv GEMM -> packed Qp/Kp/Vp
    {
        dim3 grid((3 * C_DIM) / 128, S_LEN / 128);
        gemm_f16_kernel<1><<<grid, 128, GSMEM_DYN>>>(
            S_LEN, 3 * C_DIM, C_DIM, xp_p, wtp_p, ba_p,
            nullptr, qp_p, kp_p, vp_p);
    }

    // 2) causal flash attention
    {
        cudaFuncSetAttribute(attn_f16_kernel,
                             cudaFuncAttributeMaxDynamicSharedMemorySize, ASMEM_DYN);
        dim3 grid(S_LEN / 128, H_NUM);
        attn_f16_kernel<<<grid, 256, ASMEM_DYN>>>(
            qp_p, kp_p, (const uint32_t*)vp_p, att_p);
    }

    // 3) proj GEMM -> fp32 out
    {
        dim3 grid(C_DIM / 128, S_LEN / 128);
        gemm_f16_kernel<0><<<grid, 128, GSMEM_DYN>>>(
            S_LEN, C_DIM, C_DIM, att_p, wpp_p, b_proj,
            out, nullptr, nullptr, nullptr);
    }
}

// round 10
// speedup vs baseline: 7.8578x; 1.0479x over previous
#include <cuda_runtime.h>
#include <cuda_fp16.h>
#include <cstdint>
#include <math.h>

#define S_LEN 4096
#define C_DIM 1024
#define H_NUM 16
#define HD    64
// Q pre-scale: 1/sqrt(64) * log2(e)  (softmax runs in exp2 domain)
#define QSCALE 0.18033688011112042f

// Scratch (__device__ globals). All mma-fragment-packed, fp16.
__device__ uint32_t g_qp [(size_t)H_NUM * 256 * 4 * 32 * 4];   // Q A-perm16 per head
__device__ uint32_t g_kp [(size_t)H_NUM * 512 * 4 * 32 * 2];   // K B-perm16 per head
__device__ __half   g_vp [(size_t)H_NUM * 256 * 8 * 32 * 4];   // V B-perm16 (kv-major)
__device__ uint32_t g_att[(size_t)256 * 64 * 32 * 4];          // attn out, A-perm16
__device__ uint32_t g_xp [(size_t)256 * 64 * 32 * 4];          // x, A-perm16
__device__ uint32_t g_wtp[(size_t)384 * 64 * 32 * 2];          // W_attn B-perm16 (Q pre-scaled)
__device__ uint32_t g_wpp[(size_t)128 * 64 * 32 * 2];          // W_proj B-perm16

// ---------------------------------------------------------------------------
__device__ __forceinline__ void cp16(void* s, const void* g) {
    uint32_t sa = (uint32_t)__cvta_generic_to_shared(s);
    asm volatile("cp.async.cg.shared.global [%0], [%1], 16;"
                 :: "r"(sa), "l"(__cvta_generic_to_global(g)));
}

__device__ __forceinline__ uint32_t h2u(__half2 h) {
    return *reinterpret_cast<uint32_t*>(&h);
}

// m16n8k16 fp16 mma, fp32 accum. A row-major, B col-major.
__device__ __forceinline__ void mma_f16(float c[4], const uint32_t a[4],
                                        uint32_t b0, uint32_t b1) {
    asm volatile(
        "mma.sync.aligned.m16n8k16.row.col.f32.f16.f16.f32 "
        "{%0,%1,%2,%3}, {%4,%5,%6,%7}, {%8,%9}, {%0,%1,%2,%3};"
        : "+f"(c[0]), "+f"(c[1]), "+f"(c[2]), "+f"(c[3])
        : "r"(a[0]), "r"(a[1]), "r"(a[2]), "r"(a[3]), "r"(b0), "r"(b1));
}

// ---------------------------------------------------------------------------
// Prep: A-perm16 of x [M,K]f32 -> [mb][kb16][lane][4xb32(h2)]
// ---------------------------------------------------------------------------
__global__ __launch_bounds__(256) void permA16_kernel(
    const float* __restrict__ in, uint32_t* __restrict__ out, int M, int K)
{
    int cid = blockIdx.x * 256 + threadIdx.x;
    if (cid >= (M / 16) * (K / 16) * 32) return;
    const int per_mb = (K >> 4) * 32;
    int mb  = cid / per_mb;
    int rem = cid - mb * per_mb;
    int kb  = rem >> 5;
    int lane = rem & 31;
    int g = lane >> 2, q = lane & 3;
    size_t r = mb * 16 + g, c = kb * 16 + 2 * q;
    uint4 o;
    o.x = h2u(__floats2half2_rn(in[r * K + c],           in[r * K + c + 1]));
    o.y = h2u(__floats2half2_rn(in[(r + 8) * K + c],     in[(r + 8) * K + c + 1]));
    o.z = h2u(__floats2half2_rn(in[r * K + c + 8],       in[r * K + c + 9]));
    o.w = h2u(__floats2half2_rn(in[(r + 8) * K + c + 8], in[(r + 8) * K + c + 9]));
    ((uint4*)out)[cid] = o;
}

// ---------------------------------------------------------------------------
// Prep: B-perm16 of W [K][N] -> [nb][kb16][lane][2xb32]; cols n<scaleN *= scale
// ---------------------------------------------------------------------------
__global__ __launch_bounds__(256) void permB16_kernel(
    const float* __restrict__ W, uint32_t* __restrict__ out,
    int K, int N, int scaleN, float scale)
{
    int cid = blockIdx.x * 256 + threadIdx.x;
    if (cid >= (N / 8) * (K / 16) * 32) return;
    const int per_nb = (K >> 4) * 32;
    int nb  = cid / per_nb;
    int rem = cid - nb * per_nb;
    int kb  = rem >> 5;
    int lane = rem & 31;
    int g = lane >> 2, q = lane & 3;
    size_t n = nb * 8 + g, k = kb * 16 + 2 * q;
    float s = (n < (size_t)scaleN) ? scale : 1.f;
    uint2 o;
    o.x = h2u(__floats2half2_rn(W[k * N + n] * s,       W[(k + 1) * N + n] * s));
    o.y = h2u(__floats2half2_rn(W[(k + 8) * N + n] * s, W[(k + 9) * N + n] * s));
    ((uint2*)out)[cid] = o;
}

// ---------------------------------------------------------------------------
// fp16 mma.sync GEMM, CTA 128x128, 128 threads (4 warps 2x2), warp 64x64.
// BK=32 (2 kb16), 3-stage cp.async.
// MODE 0: fp32 bias epilogue -> row-major C.  MODE 1: qkv scatter -> Qp/Kp/Vp
//   (Q section bias scaled by QSCALE in-epilogue).
// ---------------------------------------------------------------------------
#define GSTAGE_U 4096                    // u32 per stage (A 2048 + B 2048)
#define GSMEM_DYN (3 * GSTAGE_U * 4)     // 49152 B

extern __shared__ uint32_t gsm[];

template<int MODE>
__global__ __launch_bounds__(128, 2) void gemm_f16_kernel(
    int M, int N, int K,
    const uint32_t* __restrict__ Ap,
    const uint32_t* __restrict__ Bp,
    const float* __restrict__ bias,
    float* __restrict__ C,
    uint32_t* __restrict__ Qp,
    uint32_t* __restrict__ Kp,
    __half* __restrict__ Vp)
{
    const int tid  = threadIdx.x;
    const int wid  = tid >> 5;
    const int lane = tid & 31;
    const int g    = lane >> 2, q = lane & 3;
    const int bm   = blockIdx.y * 128;
    const int bn   = blockIdx.x * 128;
    const int mb0  = (wid >> 1) * 4;
    const int nb0  = (wid & 1) * 8;
    const int KB   = K >> 4;
    const int nch  = K >> 5;

    float acc[4][8][4];
#pragma unroll
    for (int i = 0; i < 4; i++)
#pragma unroll
        for (int j = 0; j < 8; j++)
#pragma unroll
            for (int e = 0; e < 4; e++) acc[i][j][e] = 0.f;

    auto load_stage = [&](int s, int ch) {
        uint32_t* As = gsm + s * GSTAGE_U;
        uint32_t* Bs = As + 2048;
        const int kb0 = ch * 2;
#pragma unroll
        for (int it = 0; it < 4; it++) {          // A: 512 x 16B
            int idx = tid + it * 128;
            int mb = idx >> 6, rem = idx & 63;
            int kb = rem >> 5, l = rem & 31;
            const uint32_t* src = Ap +
                ((size_t)((bm >> 4) + mb) * KB + kb0 + kb) * 128 + l * 4;
            cp16(As + idx * 4, src);
        }
#pragma unroll
        for (int it = 0; it < 4; it++) {          // B: 512 x 16B
            int idx = tid + it * 128;
            int nb = idx >> 5, rem = idx & 31;
            int kb = rem >> 4, ll = rem & 15;
            const uint32_t* src = Bp +
                ((size_t)((bn >> 3) + nb) * KB + kb0 + kb) * 64 + ll * 4;
            cp16(Bs + idx * 4, src);
        }
        asm volatile("cp.async.commit_group;" ::: "memory");
    };

    load_stage(0, 0);
    load_stage(1, 1);

    for (int ch = 0; ch < nch; ch++) {
        if (ch + 2 < nch)
            asm volatile("cp.async.wait_group 1;" ::: "memory");
        else
            asm volatile("cp.async.wait_group 0;" ::: "memory");
        __syncthreads();

        if (ch + 2 < nch) load_stage((ch + 2) % 3, ch + 2);

        const uint32_t* As = gsm + (ch % 3) * GSTAGE_U;
        const uint32_t* Bs = As + 2048;

#pragma unroll
        for (int kb = 0; kb < 2; kb++) {
            uint4 afr[4];
            uint2 bfr[8];
#pragma unroll
            for (int i = 0; i < 4; i++)
                afr[i] = *(const uint4*)(As + ((mb0 + i) * 2 + kb) * 128 + lane * 4);
#pragma unroll
            for (int j = 0; j < 8; j++)
                bfr[j] = *(const uint2*)(Bs + ((nb0 + j) * 2 + kb) * 64 + lane * 2);
#pragma unroll
            for (int i = 0; i < 4; i++)
#pragma unroll
                for (int j = 0; j < 8; j++)
                    mma_f16(acc[i][j], (const uint32_t*)&afr[i], bfr[j].x, bfr[j].y);
        }
    }

    if (MODE == 0) {
#pragma unroll
        for (int j = 0; j < 8; j++) {
            const int col = bn + (wid & 1) * 64 + j * 8 + 2 * q;
            const float2 bv = *(const float2*)(bias + col);
#pragma unroll
            for (int i = 0; i < 4; i++) {
                const int r0 = bm + (wid >> 1) * 64 + i * 16 + g;
                float2 o0, o1;
                o0.x = acc[i][j][0] + bv.x;
                o0.y = acc[i][j][1] + bv.y;
                o1.x = acc[i][j][2] + bv.x;
                o1.y = acc[i][j][3] + bv.y;
                *(float2*)(C + (size_t)r0 * N + col) = o0;
                *(float2*)(C + (size_t)(r0 + 8) * N + col) = o1;
            }
        }
    } else {
        // qkv scatter: section 0=Q, 1=K, 2=V; hh = head
        const int sec = bn >> 10;
        const int hh  = ((bn & 1023) >> 6) + (wid & 1);
        const float bscale = (sec == 0) ? QSCALE : 1.f;   // Q bias pre-scale
#pragma unroll
        for (int j = 0; j < 8; j++) {
            const int col = bn + (wid & 1) * 64 + j * 8 + 2 * q;
            float2 bv = *(const float2*)(bias + col);
            bv.x *= bscale; bv.y *= bscale;
#pragma unroll
            for (int i = 0; i < 4; i++) {
                float v00 = acc[i][j][0] + bv.x;    // (row g,   d 2q)
                float v01 = acc[i][j][1] + bv.y;    // (row g,   d 2q+1)
                float v10 = acc[i][j][2] + bv.x;    // (row g+8, d 2q)
                float v11 = acc[i][j][3] + bv.y;    // (row g+8, d 2q+1)
                uint32_t p0 = h2u(__floats2half2_rn(v00, v01));
                uint32_t p1 = h2u(__floats2half2_rn(v10, v11));
                if (sec == 0) {
                    const int mb = (bm >> 4) + (wid >> 1) * 4 + i;
                    const int kb = j >> 1;
                    uint32_t* base = Qp +
                        (((size_t)(hh * 256 + mb) * 4 + kb) * 32 + lane) * 4 + (j & 1) * 2;
                    base[0] = p0;
                    base[1] = p1;
                } else if (sec == 1) {
                    const int nb = (bm >> 3) + (wid >> 1) * 8 + i * 2;
                    const int kb = j >> 1;
                    uint32_t* base = Kp +
                        (((size_t)(hh * 512 + nb) * 4 + kb) * 32 + lane) * 2 + (j & 1);
                    base[0]   = p0;          // kv row g     (nb)
                    base[256] = p1;          // kv row g+8   (nb+1)
                } else {
                    // V: PV B-frag pairs run along kv; cols d=2q / 2q+1 are
                    // 4 lanes (= 16 halves) apart.
                    const int kvb = (bm >> 4) + (wid >> 1) * 4 + i;
                    const int hi  = g & 1;
                    __half* b0 = Vp +
                        ((((size_t)(hh * 256 + kvb) * 8 + j) * 32 + 2 * q * 4 + (g >> 1)) * 4);
                    __half* b1 = b0 + 16;
                    b0[hi]     = __float2half_rn(v00);
                    b0[2 + hi] = __float2half_rn(v10);
                    b1[hi]     = __float2half_rn(v01);
                    b1[2 + hi] = __float2half_rn(v11);
                }
            }
        }
    }
}

// ---------------------------------------------------------------------------
// Causal flash attention, fp16 m16n8k16, P in registers, exp2-domain softmax.
// CTA = (head, 128 q-rows), 256 threads = 8 warps. 2 CTAs/SM for phase overlap.
// ---------------------------------------------------------------------------
#define ASTAGE_U 4096                        // u32: K 2048 + V 2048
#define ASMEM_DYN (2 * ASTAGE_U * 4)         // 32768 B

extern __shared__ uint32_t asmem[];

__global__ __launch_bounds__(256, 2) void attn_f16_kernel(
    const uint32_t* __restrict__ Qp, const uint32_t* __restrict__ Kp,
    const uint32_t* __restrict__ Vp, uint32_t* __restrict__ att)
{
    const int tid   = threadIdx.x;
    const int warp  = tid >> 5;
    const int lane  = tid & 31;
    const int grp   = lane >> 2;
    const int qd    = lane & 3;
    const int h     = blockIdx.y;
    const int qtile = gridDim.x - 1 - blockIdx.x;
    const int qbase = qtile * 128;
    const int qr0   = warp * 16 + grp;
    const int njt   = 2 * qtile + 2;

    // ---- Q fragments: 4 x LDG.128 from packed Qp ----
    uint32_t qa[4][4];
    {
        const uint4* Qb = (const uint4*)(Qp +
            ((size_t)(h * 256 + qtile * 8 + warp) * 4) * 128);
#pragma unroll
        for (int ks = 0; ks < 4; ks++) {
            uint4 v = Qb[ks * 32 + lane];
            qa[ks][0] = v.x; qa[ks][1] = v.y; qa[ks][2] = v.z; qa[ks][3] = v.w;
        }
    }

    auto load_kv = [&](int s, int jt) {
        uint32_t* Ks = asmem + s * ASTAGE_U;
        uint32_t* Vs = Ks + 2048;
        const uint32_t* Kg = Kp + (size_t)(h * 512 + jt * 8) * 256;
        const uint32_t* Vg = Vp + (size_t)(h * 256 + jt * 4) * 512;
#pragma unroll
        for (int it = 0; it < 2; it++) {
            int idx = tid + it * 256;
            cp16(Ks + idx * 4, Kg + idx * 4);
            cp16(Vs + idx * 4, Vg + idx * 4);
        }
        asm volatile("cp.async.commit_group;" ::: "memory");
    };

    load_kv(0, 0);

    float o[8][4];
#pragma unroll
    for (int nt = 0; nt < 8; nt++)
#pragma unroll
        for (int e = 0; e < 4; e++) o[nt][e] = 0.f;
    float m0 = -INFINITY, m1 = -INFINITY, l0 = 0.f, l1 = 0.f;

    for (int jt = 0; jt < njt; jt++) {
        const int s = jt & 1;
        if (jt) __syncthreads();
        if (jt + 1 < njt) load_kv(s ^ 1, jt + 1);
        if (jt + 1 < njt)
            asm volatile("cp.async.wait_group 1;" ::: "memory");
        else
            asm volatile("cp.async.wait_group 0;" ::: "memory");
        __syncthreads();

        if (warp < 4 && jt == njt - 1) continue;    // fully future-masked

        const uint32_t* Ks = asmem + s * ASTAGE_U;
        const uint32_t* Vs = Ks + 2048;
        const int kvbase = jt * 64;

        // ---- S = Q K^T (exp2 domain: Q pre-scaled by 0.125*log2e) ----
        float sv[8][4];
#pragma unroll
        for (int nt = 0; nt < 8; nt++)
#pragma unroll
            for (int e = 0; e < 4; e++) sv[nt][e] = 0.f;

#pragma unroll
        for (int ks = 0; ks < 4; ks++) {
#pragma unroll
            for (int nt = 0; nt < 8; nt++) {
                uint2 b = *(const uint2*)(Ks + ((nt * 4 + ks) * 32 + lane) * 2);
                mma_f16(sv[nt], qa[ks], b.x, b.y);
            }
        }

        // ---- causal mask ----
        if (jt >= 2 * qtile) {
            const int rg0 = qbase + qr0, rg1 = rg0 + 8;
#pragma unroll
            for (int nt = 0; nt < 8; nt++) {
                int cg = kvbase + nt * 8 + qd * 2;
                if (cg     > rg0) sv[nt][0] = -INFINITY;
                if (cg + 1 > rg0) sv[nt][1] = -INFINITY;
                if (cg     > rg1) sv[nt][2] = -INFINITY;
                if (cg + 1 > rg1) sv[nt][3] = -INFINITY;
            }
        }

        // ---- online softmax (exp2 domain) ----
        float mt0 = -INFINITY, mt1 = -INFINITY;
#pragma unroll
        for (int nt = 0; nt < 8; nt++) {
            mt0 = fmaxf(mt0, fmaxf(sv[nt][0], sv[nt][1]));
            mt1 = fmaxf(mt1, fmaxf(sv[nt][2], sv[nt][3]));
        }
        mt0 = fmaxf(mt0, __shfl_xor_sync(0xffffffffu, mt0, 1));
        mt0 = fmaxf(mt0, __shfl_xor_sync(0xffffffffu, mt0, 2));
        mt1 = fmaxf(mt1, __shfl_xor_sync(0xffffffffu, mt1, 1));
        mt1 = fmaxf(mt1, __shfl_xor_sync(0xffffffffu, mt1, 2));

        const float mn0 = fmaxf(m0, mt0), mn1 = fmaxf(m1, mt1);
        const float al0 = exp2f(m0 - mn0), al1 = exp2f(m1 - mn1);
        m0 = mn0; m1 = mn1;

        float rs0 = 0.f, rs1 = 0.f;
#pragma unroll
        for (int nt = 0; nt < 8; nt++) {
            sv[nt][0] = exp2f(sv[nt][0] - mn0);
            sv[nt][1] = exp2f(sv[nt][1] - mn0);
            sv[nt][2] = exp2f(sv[nt][2] - mn1);
            sv[nt][3] = exp2f(sv[nt][3] - mn1);
            rs0 += sv[nt][0] + sv[nt][1];
            rs1 += sv[nt][2] + sv[nt][3];
        }
        rs0 += __shfl_xor_sync(0xffffffffu, rs0, 1);
        rs0 += __shfl_xor_sync(0xffffffffu, rs0, 2);
        rs1 += __shfl_xor_sync(0xffffffffu, rs1, 1);
        rs1 += __shfl_xor_sync(0xffffffffu, rs1, 2);
        l0 = l0 * al0 + rs0;
        l1 = l1 * al1 + rs1;

#pragma unroll
        for (int nt = 0; nt < 8; nt++) {
            o[nt][0] *= al0; o[nt][1] *= al0;
            o[nt][2] *= al1; o[nt][3] *= al1;
        }

        // ---- P: pack C-frags directly into PV A-frags (registers only) ----
        uint32_t p0[8], p1[8];
#pragma unroll
        for (int nt = 0; nt < 8; nt++) {
            p0[nt] = h2u(__floats2half2_rn(sv[nt][0], sv[nt][1]));
            p1[nt] = h2u(__floats2half2_rn(sv[nt][2], sv[nt][3]));
        }

        // ---- O += P V ----
#pragma unroll
        for (int ks = 0; ks < 4; ks++) {
            uint32_t pa[4] = { p0[2 * ks], p1[2 * ks], p0[2 * ks + 1], p1[2 * ks + 1] };
#pragma unroll
            for (int nt = 0; nt < 8; nt++) {
                uint2 b = *(const uint2*)(Vs + ((ks * 8 + nt) * 32 + lane) * 2);
                mma_f16(o[nt], pa, b.x, b.y);
            }
        }
    }

    // ---- epilogue: normalize + fp16 round, store g_att in A-perm16 ----
    const float i0 = 1.f / l0, i1 = 1.f / l1;
    const int mb = qtile * 8 + warp;
#pragma unroll
    for (int nt = 0; nt < 8; nt++) {
        const int kb = h * 4 + (nt >> 1);
        uint32_t* base = att +
            (((size_t)mb * 64 + kb) * 32 + lane) * 4 + (nt & 1) * 2;
        base[0] = h2u(__floats2half2_rn(o[nt][0] * i0, o[nt][1] * i0));
        base[1] = h2u(__floats2half2_rn(o[nt][2] * i1, o[nt][3] * i1));
    }
}

// ---------------------------------------------------------------------------
// Launch
// ---------------------------------------------------------------------------
extern "C" void kernel_launch(void* const* d_in, const int* in_sizes, int n_in,
                              void* d_out, int out_size)
{
    const float* x      = (const float*)d_in[0];
    // d_in[1] = attention_mask: exact causal triu -> handled analytically
    const float* W_attn = (const float*)d_in[2];
    const float* b_attn = (const float*)d_in[3];
    const float* W_proj = (const float*)d_in[4];
    const float* b_proj = (const float*)d_in[5];
    float* out = (float*)d_out;

    uint32_t *qp_p, *kp_p, *att_p, *xp_p, *wtp_p, *wpp_p;
    __half* vp_p;
    cudaGetSymbolAddress((void**)&qp_p,  g_qp);
    cudaGetSymbolAddress((void**)&kp_p,  g_kp);
    cudaGetSymbolAddress((void**)&vp_p,  g_vp);
    cudaGetSymbolAddress((void**)&att_p, g_att);
    cudaGetSymbolAddress((void**)&xp_p,  g_xp);
    cudaGetSymbolAddress((void**)&wtp_p, g_wtp);
    cudaGetSymbolAddress((void**)&wpp_p, g_wpp);

    // 0) prep: fp16 permuted operands (Q cols of W_attn get QSCALE)
    {
        int nA = 256 * 64 * 32;
        permA16_kernel<<<(nA + 255) / 256, 256>>>(x, xp_p, S_LEN, C_DIM);

        int nB1 = 384 * 64 * 32;
        permB16_kernel<<<(nB1 + 255) / 256, 256>>>(
            W_attn, wtp_p, C_DIM, 3 * C_DIM, C_DIM, QSCALE);

        int nB2 = 128 * 64 * 32;
        permB16_kernel<<<(nB2 + 255) / 256, 256>>>(
            W_proj, wpp_p, C_DIM, C_DIM, 0, 1.f);
    }

    cudaFuncSetAttribute(gemm_f16_kernel<0>,
                         cudaFuncAttributeMaxDynamicSharedMemorySize, GSMEM_DYN);
    cudaFuncSetAttribute(gemm_f16_kernel<1>,
                         cudaFuncAttributeMaxDynamicSharedMemorySize, GSMEM_DYN);

    // 1) qkv GEMM -> packed Qp/Kp/Vp
    {
        dim3 grid((3 * C_DIM) / 128, S_LEN / 128);
        gemm_f16_kernel<1><<<grid, 128, GSMEM_DYN>>>(
            S_LEN, 3 * C_DIM, C_DIM, xp_p, wtp_p, b_attn,
            nullptr, qp_p, kp_p, vp_p);
    }

    // 2) causal flash attention
    {
        cudaFuncSetAttribute(attn_f16_kernel,
                             cudaFuncAttributeMaxDynamicSharedMemorySize, ASMEM_DYN);
        dim3 grid(S_LEN / 128, H_NUM);
        attn_f16_kernel<<<grid, 256, ASMEM_DYN>>>(
            qp_p, kp_p, (const uint32_t*)vp_p, att_p);
    }

    // 3) proj GEMM -> fp32 out
    {
        dim3 grid(C_DIM / 128, S_LEN / 128);
        gemm_f16_kernel<0><<<grid, 128, GSMEM_DYN>>>(
            S_LEN, C_DIM, C_DIM, att_p, wpp_p, b_proj,
            out, nullptr, nullptr, nullptr);
    }
}